// round 13
// baseline (speedup 1.0000x reference)
#include <cuda_runtime.h>
#include <cuda_bf16.h>
#include <cstdint>

#define N_NODES  50000
#define N_EDGES  800000
#define N_GRAPHS 64
#define IN_DIM   384
#define HID      128
#define SCB      196
#define T64_ALL  ((N_NODES + 63) / 64)       // 782

// ---- plain gemm smem (K-chunk staged A+B, from R12) ----
#define STG_A_LO 5120
#define STG_B_HI 10240
#define STG_B_LO 18944
#define STG_SZ   27648
#define GEMM_SMEM (2 * STG_SZ)

// ---- fused gemm smem: A fully staged (64x136 bf16 hi+lo), B double-buffered ----
#define FA_LO   17408
#define FB_BASE 34816
#define FB_STG  17408        // B_hi 8704 + B_lo 8704
#define FGEMM_SMEM (FB_BASE + 2 * FB_STG)   // 69632

// ================= streams/events =================
struct HxStreams {
    cudaStream_t s1;
    cudaEvent_t e_root, e_csr;
    HxStreams() {
        cudaStreamCreateWithFlags(&s1, cudaStreamNonBlocking);
        cudaEventCreateWithFlags(&e_root, cudaEventDisableTiming);
        cudaEventCreateWithFlags(&e_csr, cudaEventDisableTiming);
    }
};
static HxStreams g_hx;

// ================= scratch =================
__device__ float g_dis[N_NODES];
__device__ float g_ha[N_NODES * HID];
__device__ float g_hb[N_NODES * HID];
__device__ float g_act[N_NODES * HID];
__device__ float g_pool[N_GRAPHS * HID];
__device__ float g_cnt[N_GRAPHS];
__device__ int   g_cntarr[N_NODES];
__device__ int   g_scan[N_NODES];
__device__ int   g_bsum[256];
__device__ int   g_boff[256];
__device__ int   g_rowptr[N_NODES + 1];
__device__ int   g_cursor[N_NODES];
__device__ int   g_csrc[N_EDGES];

__device__ __forceinline__ uint32_t smem_u32(const void* p) {
    uint32_t a;
    asm("{ .reg .u64 t; cvta.to.shared.u64 t, %1; cvt.u32.u64 %0, t; }" : "=r"(a) : "l"(p));
    return a;
}
__device__ __forceinline__ void split2(float f0, float f1, uint32_t& h, uint32_t& l) {
    asm("cvt.rn.bf16x2.f32 %0, %1, %2;" : "=r"(h) : "f"(f1), "f"(f0));
    float h0 = __uint_as_float(h << 16);
    float h1 = __uint_as_float(h & 0xFFFF0000u);
    float l0 = f0 - h0, l1 = f1 - h1;
    asm("cvt.rn.bf16x2.f32 %0, %1, %2;" : "=r"(l) : "f"(l1), "f"(l0));
}

#define LDSM_X4(r, a)                                                          \
    asm volatile("ldmatrix.sync.aligned.m8n8.x4.shared.b16 {%0,%1,%2,%3}, [%4];" \
                 : "=r"((r)[0]), "=r"((r)[1]), "=r"((r)[2]), "=r"((r)[3]) : "r"(a))
#define LDSM_X4T(r, a)                                                         \
    asm volatile("ldmatrix.sync.aligned.m8n8.x4.trans.shared.b16 {%0,%1,%2,%3}, [%4];" \
                 : "=r"((r)[0]), "=r"((r)[1]), "=r"((r)[2]), "=r"((r)[3]) : "r"(a))
#define MMA_BF16(c, a, b0, b1)                                                 \
    asm volatile("mma.sync.aligned.m16n8k16.row.col.f32.bf16.bf16.f32 "        \
                 "{%0,%1,%2,%3}, {%4,%5,%6,%7}, {%8,%9}, {%0,%1,%2,%3};"       \
                 : "+f"((c)[0]), "+f"((c)[1]), "+f"((c)[2]), "+f"((c)[3])      \
                 : "r"((a)[0]), "r"((a)[1]), "r"((a)[2]), "r"((a)[3]),         \
                   "r"(b0), "r"(b1))

// ================= setup kernels =================
__global__ void k_zero() {
    int i = blockIdx.x * blockDim.x + threadIdx.x;
    if (i < N_NODES)        g_cntarr[i] = 0;
    if (i < N_GRAPHS * HID) g_pool[i] = 0.f;
    if (i < N_GRAPHS)       g_cnt[i] = 0.f;
}
__global__ void k_count_edges(const int* __restrict__ dst) {
    int e = blockIdx.x * blockDim.x + threadIdx.x;
    if (e < N_EDGES) atomicAdd(&g_cntarr[dst[e]], 1);
}
__global__ void k_scan1() {
    __shared__ int s[256];
    int tid = threadIdx.x;
    int i = blockIdx.x * 256 + tid;
    s[tid] = (i < N_NODES) ? g_cntarr[i] : 0;
    __syncthreads();
#pragma unroll
    for (int off = 1; off < 256; off <<= 1) {
        int t = (tid >= off) ? s[tid - off] : 0;
        __syncthreads();
        s[tid] += t;
        __syncthreads();
    }
    if (i < N_NODES) g_scan[i] = s[tid];
    if (tid == 255) g_bsum[blockIdx.x] = s[255];
}
__global__ void k_scan2() {
    __shared__ int s[256];
    int tid = threadIdx.x;
    int v = (tid < SCB) ? g_bsum[tid] : 0;
    s[tid] = v;
    __syncthreads();
#pragma unroll
    for (int off = 1; off < 256; off <<= 1) {
        int t = (tid >= off) ? s[tid - off] : 0;
        __syncthreads();
        s[tid] += t;
        __syncthreads();
    }
    g_boff[tid] = s[tid] - v;
}
__global__ void k_scan3() {
    int i = blockIdx.x * blockDim.x + threadIdx.x;
    if (i < N_NODES) {
        int cnt = g_cntarr[i];
        int S = g_scan[i] + g_boff[i >> 8];
        g_rowptr[i + 1] = S;
        g_cursor[i] = S - cnt;
        g_dis[i] = rsqrtf((float)cnt + 1.f);
        if (i == 0) g_rowptr[0] = 0;
    }
}
__global__ void k_fill(const int* __restrict__ src, const int* __restrict__ dst) {
    int e = blockIdx.x * blockDim.x + threadIdx.x;
    if (e < N_EDGES) {
        int d = dst[e];
        int pos = atomicAdd(&g_cursor[d], 1);
        g_csrc[pos] = src[e];
    }
}

// ================= plain split-bf16 GEMM (layer 1: x @ W1 -> g_ha raw) =================
template <int K>
__global__ void __launch_bounds__(256)
k_gemm(const float* __restrict__ A, const float* __restrict__ W, float* __restrict__ Hout) {
    extern __shared__ char smx[];
    const int tid = threadIdx.x;
    const int lane = tid & 31;
    const int wid = tid >> 5;
    const int wm = wid & 1;
    const int wn = wid >> 1;
    const int m0 = blockIdx.x * 64;

    const int ar = tid >> 2;
    const int ac = (tid & 3) * 8;
    const int br = tid >> 4;
    const int bc = (tid & 15) * 8;

    const uint32_t sbase = smem_u32(smx);
    float4 sa0, sa1, sb0, sb1, sb2, sb3;

    auto ldg_chunk = [&](int k0) {
        int row = m0 + ar;
        int rc = (row < N_NODES) ? row : (N_NODES - 1);
        const float* ap = A + (long)rc * K + k0 + ac;
        sa0 = *(const float4*)ap;
        sa1 = *(const float4*)(ap + 4);
        const float* bp = W + (long)(k0 + br) * 128 + bc;
        sb0 = *(const float4*)bp;
        sb1 = *(const float4*)(bp + 4);
        const float* bp2 = W + (long)(k0 + br + 16) * 128 + bc;
        sb2 = *(const float4*)bp2;
        sb3 = *(const float4*)(bp2 + 4);
    };
    auto sts_chunk = [&](int s) {
        char* base = smx + s * STG_SZ;
        uint32_t h0, h1, h2, h3, l0, l1, l2, l3;
        split2(sa0.x, sa0.y, h0, l0); split2(sa0.z, sa0.w, h1, l1);
        split2(sa1.x, sa1.y, h2, l2); split2(sa1.z, sa1.w, h3, l3);
        *(uint4*)(base + (ar * 40 + ac) * 2)            = make_uint4(h0, h1, h2, h3);
        *(uint4*)(base + STG_A_LO + (ar * 40 + ac) * 2) = make_uint4(l0, l1, l2, l3);
        split2(sb0.x, sb0.y, h0, l0); split2(sb0.z, sb0.w, h1, l1);
        split2(sb1.x, sb1.y, h2, l2); split2(sb1.z, sb1.w, h3, l3);
        *(uint4*)(base + STG_B_HI + (br * 136 + bc) * 2) = make_uint4(h0, h1, h2, h3);
        *(uint4*)(base + STG_B_LO + (br * 136 + bc) * 2) = make_uint4(l0, l1, l2, l3);
        split2(sb2.x, sb2.y, h0, l0); split2(sb2.z, sb2.w, h1, l1);
        split2(sb3.x, sb3.y, h2, l2); split2(sb3.z, sb3.w, h3, l3);
        *(uint4*)(base + STG_B_HI + ((br + 16) * 136 + bc) * 2) = make_uint4(h0, h1, h2, h3);
        *(uint4*)(base + STG_B_LO + ((br + 16) * 136 + bc) * 2) = make_uint4(l0, l1, l2, l3);
    };

    float c[2][4][4] = {};
    constexpr int NC = K / 32;
    ldg_chunk(0);
    sts_chunk(0);
    __syncthreads();
    if (NC > 1) ldg_chunk(32);

    for (int ch = 0; ch < NC; ch++) {
        if (ch + 1 < NC) sts_chunk((ch + 1) & 1);
        if (ch + 2 < NC) ldg_chunk((ch + 2) * 32);
        uint32_t st = sbase + (ch & 1) * STG_SZ;
#pragma unroll
        for (int ks = 0; ks < 2; ks++) {
            uint32_t Ah[2][4], Al[2][4], Bh[2][4], Bl[2][4];
#pragma unroll
            for (int mt = 0; mt < 2; mt++) {
                uint32_t row = wm * 32 + mt * 16 + (lane & 15);
                uint32_t col = ks * 16 + (lane >> 4) * 8;
                uint32_t ad = st + (row * 40 + col) * 2;
                LDSM_X4(Ah[mt], ad);
                LDSM_X4(Al[mt], ad + STG_A_LO);
            }
#pragma unroll
            for (int g2 = 0; g2 < 2; g2++) {
                uint32_t brow = ks * 16 + (lane & 15);
                uint32_t bcol = wn * 32 + g2 * 16 + (lane >> 4) * 8;
                uint32_t bd = st + STG_B_HI + (brow * 136 + bcol) * 2;
                LDSM_X4T(Bh[g2], bd);
                LDSM_X4T(Bl[g2], bd + (STG_B_LO - STG_B_HI));
            }
#pragma unroll
            for (int mt = 0; mt < 2; mt++)
#pragma unroll
                for (int nt = 0; nt < 4; nt++) {
                    uint32_t b0h = Bh[nt >> 1][(nt & 1) * 2], b1h = Bh[nt >> 1][(nt & 1) * 2 + 1];
                    uint32_t b0l = Bl[nt >> 1][(nt & 1) * 2], b1l = Bl[nt >> 1][(nt & 1) * 2 + 1];
                    MMA_BF16(c[mt][nt], Ah[mt], b0h, b1h);
                    MMA_BF16(c[mt][nt], Ah[mt], b0l, b1l);
                    MMA_BF16(c[mt][nt], Al[mt], b0h, b1h);
                }
        }
        __syncthreads();
    }

    const int g = lane >> 2, t = lane & 3;
#pragma unroll
    for (int mt = 0; mt < 2; mt++) {
        int r0 = m0 + wm * 32 + mt * 16 + g;
        int r1 = r0 + 8;
#pragma unroll
        for (int nt = 0; nt < 4; nt++) {
            int col = wn * 32 + nt * 8 + t * 2;
            if (r0 < N_NODES)
                *(float2*)&Hout[r0 * 128 + col] = make_float2(c[mt][nt][0], c[mt][nt][1]);
            if (r1 < N_NODES)
                *(float2*)&Hout[r1 * 128 + col] = make_float2(c[mt][nt][2], c[mt][nt][3]);
        }
    }
}

// ================= fused agg+GEMM (layers 2,3) =================
// A_eff[n] = relu( dn*( own + sum_neighbors ) + bias ), gathered from Hin via CSR,
// staged fully in smem as bf16 hi/lo; C = A_eff @ W; Hout = C * dis[row] (pre-scaled).
// WEIGHTED: Hin raw -> own = h[n]*dn, neighbor term h[s]*dis[s].
// else:     Hin pre-scaled -> own = h[n], neighbor term h[s].
template <bool WEIGHTED>
__global__ void __launch_bounds__(256)
k_fgemm(const float* __restrict__ Hin, float* __restrict__ Hout,
        const float* __restrict__ W, const float* __restrict__ bias) {
    extern __shared__ char smx[];
    const int tid = threadIdx.x;
    const int lane = tid & 31;
    const int wid = tid >> 5;
    const int wm = wid & 1;
    const int wn = wid >> 1;
    const int m0 = blockIdx.x * 64;

    const uint32_t sbase = smem_u32(smx);

    // ---- B staging (identical pattern to k_gemm) ----
    const int br = tid >> 4;
    const int bc = (tid & 15) * 8;
    float4 sb0, sb1, sb2, sb3;
    auto ldgB = [&](int k0) {
        const float* bp = W + (long)(k0 + br) * 128 + bc;
        sb0 = *(const float4*)bp;
        sb1 = *(const float4*)(bp + 4);
        const float* bp2 = W + (long)(k0 + br + 16) * 128 + bc;
        sb2 = *(const float4*)bp2;
        sb3 = *(const float4*)(bp2 + 4);
    };
    auto stsB = [&](int s) {
        char* base = smx + FB_BASE + s * FB_STG;
        uint32_t h0, h1, h2, h3, l0, l1, l2, l3;
        split2(sb0.x, sb0.y, h0, l0); split2(sb0.z, sb0.w, h1, l1);
        split2(sb1.x, sb1.y, h2, l2); split2(sb1.z, sb1.w, h3, l3);
        *(uint4*)(base + (br * 136 + bc) * 2)        = make_uint4(h0, h1, h2, h3);
        *(uint4*)(base + 8704 + (br * 136 + bc) * 2) = make_uint4(l0, l1, l2, l3);
        split2(sb2.x, sb2.y, h0, l0); split2(sb2.z, sb2.w, h1, l1);
        split2(sb3.x, sb3.y, h2, l2); split2(sb3.z, sb3.w, h3, l3);
        *(uint4*)(base + ((br + 16) * 136 + bc) * 2)        = make_uint4(h0, h1, h2, h3);
        *(uint4*)(base + 8704 + ((br + 16) * 136 + bc) * 2) = make_uint4(l0, l1, l2, l3);
    };

    ldgB(0);   // chunk-0 B in flight during the gather

    // ---- gather + activation: thread owns (row ar, cols q*32..q*32+31) ----
    {
        const int ar = tid >> 2;
        const int q = tid & 3;
        int n = m0 + ar;
        int nc_ = (n < N_NODES) ? n : (N_NODES - 1);
        int rp0 = g_rowptr[nc_], rp1 = g_rowptr[nc_ + 1];
        float dn = g_dis[nc_];
        const float* hn = Hin + (long)nc_ * 128 + q * 32;

        float4 acc[8];
#pragma unroll
        for (int j = 0; j < 8; j++) {
            float4 v = *(const float4*)&hn[j * 4];
            if (WEIGHTED) { v.x *= dn; v.y *= dn; v.z *= dn; v.w *= dn; }
            acc[j] = v;
        }
        int i = rp0;
        for (; i + 1 < rp1; i += 2) {
            int s0 = g_csrc[i], s1 = g_csrc[i + 1];
            const float* p0 = Hin + (long)s0 * 128 + q * 32;
            const float* p1 = Hin + (long)s1 * 128 + q * 32;
            if (WEIGHTED) {
                float w0 = g_dis[s0], w1 = g_dis[s1];
#pragma unroll
                for (int j = 0; j < 8; j++) {
                    float4 v0 = *(const float4*)&p0[j * 4];
                    float4 v1 = *(const float4*)&p1[j * 4];
                    acc[j].x += v0.x * w0 + v1.x * w1;
                    acc[j].y += v0.y * w0 + v1.y * w1;
                    acc[j].z += v0.z * w0 + v1.z * w1;
                    acc[j].w += v0.w * w0 + v1.w * w1;
                }
            } else {
#pragma unroll
                for (int j = 0; j < 8; j++) {
                    float4 v0 = *(const float4*)&p0[j * 4];
                    float4 v1 = *(const float4*)&p1[j * 4];
                    acc[j].x += v0.x + v1.x;
                    acc[j].y += v0.y + v1.y;
                    acc[j].z += v0.z + v1.z;
                    acc[j].w += v0.w + v1.w;
                }
            }
        }
        if (i < rp1) {
            int s0 = g_csrc[i];
            const float* p0 = Hin + (long)s0 * 128 + q * 32;
            float w0 = WEIGHTED ? g_dis[s0] : 1.f;
#pragma unroll
            for (int j = 0; j < 8; j++) {
                float4 v0 = *(const float4*)&p0[j * 4];
                acc[j].x += v0.x * w0;
                acc[j].y += v0.y * w0;
                acc[j].z += v0.z * w0;
                acc[j].w += v0.w * w0;
            }
        }
        // act = relu(acc*dn + bias); split -> A_hi/A_lo
#pragma unroll
        for (int j = 0; j < 8; j++) {
            float4 b = *(const float4*)&bias[q * 32 + j * 4];
            float a0 = fmaxf(fmaf(acc[j].x, dn, b.x), 0.f);
            float a1 = fmaxf(fmaf(acc[j].y, dn, b.y), 0.f);
            float a2 = fmaxf(fmaf(acc[j].z, dn, b.z), 0.f);
            float a3 = fmaxf(fmaf(acc[j].w, dn, b.w), 0.f);
            uint32_t h0, h1, l0, l1;
            split2(a0, a1, h0, l0);
            split2(a2, a3, h1, l1);
            int off = (ar * 136 + q * 32 + j * 4) * 2;
            *(uint2*)(smx + off)         = make_uint2(h0, h1);
            *(uint2*)(smx + FA_LO + off) = make_uint2(l0, l1);
        }
    }

    stsB(0);
    __syncthreads();
    ldgB(32);

    float c[2][4][4] = {};
    for (int ch = 0; ch < 4; ch++) {
        if (ch + 1 < 4) stsB((ch + 1) & 1);
        if (ch + 2 < 4) ldgB((ch + 2) * 32);
        uint32_t st = sbase + FB_BASE + (ch & 1) * FB_STG;
#pragma unroll
        for (int ks = 0; ks < 2; ks++) {
            uint32_t Ah[2][4], Al[2][4], Bh[2][4], Bl[2][4];
#pragma unroll
            for (int mt = 0; mt < 2; mt++) {
                uint32_t row = wm * 32 + mt * 16 + (lane & 15);
                uint32_t col = ch * 32 + ks * 16 + (lane >> 4) * 8;
                uint32_t ad = sbase + (row * 136 + col) * 2;
                LDSM_X4(Ah[mt], ad);
                LDSM_X4(Al[mt], ad + FA_LO);
            }
#pragma unroll
            for (int g2 = 0; g2 < 2; g2++) {
                uint32_t brow = ks * 16 + (lane & 15);
                uint32_t bcol = wn * 32 + g2 * 16 + (lane >> 4) * 8;
                uint32_t bd = st + (brow * 136 + bcol) * 2;
                LDSM_X4T(Bh[g2], bd);
                LDSM_X4T(Bl[g2], bd + 8704);
            }
#pragma unroll
            for (int mt = 0; mt < 2; mt++)
#pragma unroll
                for (int nt = 0; nt < 4; nt++) {
                    uint32_t b0h = Bh[nt >> 1][(nt & 1) * 2], b1h = Bh[nt >> 1][(nt & 1) * 2 + 1];
                    uint32_t b0l = Bl[nt >> 1][(nt & 1) * 2], b1l = Bl[nt >> 1][(nt & 1) * 2 + 1];
                    MMA_BF16(c[mt][nt], Ah[mt], b0h, b1h);
                    MMA_BF16(c[mt][nt], Ah[mt], b0l, b1l);
                    MMA_BF16(c[mt][nt], Al[mt], b0h, b1h);
                }
        }
        __syncthreads();
    }

    const int g = lane >> 2, t = lane & 3;
#pragma unroll
    for (int mt = 0; mt < 2; mt++) {
        int r0 = m0 + wm * 32 + mt * 16 + g;
        int r1 = r0 + 8;
        float s0 = (r0 < N_NODES) ? g_dis[r0] : 0.f;
        float s1 = (r1 < N_NODES) ? g_dis[r1] : 0.f;
#pragma unroll
        for (int nt = 0; nt < 4; nt++) {
            int col = wn * 32 + nt * 8 + t * 2;
            if (r0 < N_NODES)
                *(float2*)&Hout[r0 * 128 + col] = make_float2(c[mt][nt][0] * s0, c[mt][nt][1] * s0);
            if (r1 < N_NODES)
                *(float2*)&Hout[r1 * 128 + col] = make_float2(c[mt][nt][2] * s1, c[mt][nt][3] * s1);
        }
    }
}

// ================= final aggregation (layer 3, h pre-scaled) =================
__global__ void __launch_bounds__(256)
k_agg(const float* __restrict__ Hin, const float* __restrict__ bias) {
    int wid = threadIdx.x >> 5;
    int lane = threadIdx.x & 31;
    int node = blockIdx.x * 8 + wid;
    if (node >= N_NODES) return;

    int rp0 = g_rowptr[node];
    int rp1 = g_rowptr[node + 1];
    float dn = g_dis[node];
    int l4 = lane * 4;

    float4 acc = *(const float4*)&Hin[node * 128 + l4];
    int i = rp0;
    for (; i + 3 < rp1; i += 4) {
        int s0 = g_csrc[i], s1 = g_csrc[i + 1], s2 = g_csrc[i + 2], s3 = g_csrc[i + 3];
        float4 v0 = *(const float4*)&Hin[s0 * 128 + l4];
        float4 v1 = *(const float4*)&Hin[s1 * 128 + l4];
        float4 v2 = *(const float4*)&Hin[s2 * 128 + l4];
        float4 v3 = *(const float4*)&Hin[s3 * 128 + l4];
        acc.x += (v0.x + v1.x) + (v2.x + v3.x);
        acc.y += (v0.y + v1.y) + (v2.y + v3.y);
        acc.z += (v0.z + v1.z) + (v2.z + v3.z);
        acc.w += (v0.w + v1.w) + (v2.w + v3.w);
    }
    for (; i < rp1; i++) {
        int s0 = g_csrc[i];
        float4 v0 = *(const float4*)&Hin[s0 * 128 + l4];
        acc.x += v0.x; acc.y += v0.y; acc.z += v0.z; acc.w += v0.w;
    }

    float4 b = *(const float4*)&bias[l4];
    acc.x = fmaxf(fmaf(acc.x, dn, b.x), 0.f);
    acc.y = fmaxf(fmaf(acc.y, dn, b.y), 0.f);
    acc.z = fmaxf(fmaf(acc.z, dn, b.z), 0.f);
    acc.w = fmaxf(fmaf(acc.w, dn, b.w), 0.f);
    *(float4*)&g_act[node * 128 + l4] = acc;
}

// ================= pooling + MLP =================
__global__ void __launch_bounds__(128)
k_poolseg(const int* __restrict__ batch) {
    __shared__ int sb[128];
    int t = threadIdx.x;
    int n0 = blockIdx.x * 128;
    int cnt = min(128, N_NODES - n0);
    if (t < cnt) sb[t] = batch[n0 + t];
    __syncthreads();

    float acc = 0.f;
    int cur = sb[0];
    int segstart = 0;
    for (int i = 0; i < cnt; i++) {
        int g = sb[i];
        if (g != cur) {
            atomicAdd(&g_pool[cur * 128 + t], acc);
            if (t == 0) atomicAdd(&g_cnt[cur], (float)(i - segstart));
            acc = 0.f;
            cur = g;
            segstart = i;
        }
        acc += g_act[(n0 + i) * 128 + t];
    }
    atomicAdd(&g_pool[cur * 128 + t], acc);
    if (t == 0) atomicAdd(&g_cnt[cur], (float)(cnt - segstart));
}

__global__ void k_mlp(const float* __restrict__ Wm1, const float* __restrict__ bm1,
                      const float* __restrict__ Wm2, const float* __restrict__ bm2,
                      float* __restrict__ out) {
    int g = blockIdx.x;
    int j = threadIdx.x;
    __shared__ float p[128];
    __shared__ float red[64];
    float cnt = fmaxf(g_cnt[g], 1.f);
    p[j] = g_pool[g * 128 + j] / cnt;
    p[j + 64] = g_pool[g * 128 + 64 + j] / cnt;
    __syncthreads();
    float z = bm1[j];
#pragma unroll 8
    for (int k = 0; k < 128; k++) z = fmaf(p[k], Wm1[k * 64 + j], z);
    z = fmaxf(z, 0.f);
    z *= Wm2[j];
    red[j] = z;
    __syncthreads();
#pragma unroll
    for (int s = 32; s > 0; s >>= 1) {
        if (j < s) red[j] += red[j + s];
        __syncthreads();
    }
    if (j == 0) out[g] = red[0] + bm2[0];
}

// ================= launch =================
extern "C" void kernel_launch(void* const* d_in, const int* in_sizes, int n_in,
                              void* d_out, int out_size) {
    const float* x    = (const float*)d_in[0];
    const int*   ei   = (const int*)  d_in[1];
    const int*   batch= (const int*)  d_in[2];
    const float* W1   = (const float*)d_in[3];
    const float* b1   = (const float*)d_in[4];
    const float* W2   = (const float*)d_in[5];
    const float* b2   = (const float*)d_in[6];
    const float* W3   = (const float*)d_in[7];
    const float* b3   = (const float*)d_in[8];
    const float* Wm1  = (const float*)d_in[9];
    const float* bm1  = (const float*)d_in[10];
    const float* Wm2  = (const float*)d_in[11];
    const float* bm2  = (const float*)d_in[12];
    const int* src = ei;
    const int* dst = ei + N_EDGES;
    float* out = (float*)d_out;
    cudaStream_t s1 = g_hx.s1;

    cudaFuncSetAttribute(k_gemm<IN_DIM>,  cudaFuncAttributeMaxDynamicSharedMemorySize, GEMM_SMEM);
    cudaFuncSetAttribute(k_fgemm<true>,   cudaFuncAttributeMaxDynamicSharedMemorySize, FGEMM_SMEM);
    cudaFuncSetAttribute(k_fgemm<false>,  cudaFuncAttributeMaxDynamicSharedMemorySize, FGEMM_SMEM);

    const int EB = (N_EDGES + 255) / 256;
    const int AB = (N_NODES + 7) / 8;
    const int PB = (N_NODES + 127) / 128;

    // fork: CSR build on s1 || layer-1 GEMM on s0
    cudaEventRecord(g_hx.e_root, 0);
    cudaStreamWaitEvent(s1, g_hx.e_root, 0);

    k_zero       <<<SCB, 256, 0, s1>>>();
    k_count_edges<<<EB, 256, 0, s1>>>(dst);
    k_scan1      <<<SCB, 256, 0, s1>>>();
    k_scan2      <<<1, 256, 0, s1>>>();
    k_scan3      <<<SCB, 256, 0, s1>>>();
    k_fill       <<<EB, 256, 0, s1>>>(src, dst);
    cudaEventRecord(g_hx.e_csr, s1);

    k_gemm<IN_DIM><<<T64_ALL, 256, GEMM_SMEM>>>(x, W1, g_ha);

    cudaStreamWaitEvent(0, g_hx.e_csr, 0);

    // layer 2: fused agg(h_a raw, weighted) + gemm -> g_hb (pre-scaled)
    k_fgemm<true><<<T64_ALL, 256, FGEMM_SMEM>>>(g_ha, g_hb, W2, b1);
    // layer 3: fused agg(h_b pre-scaled) + gemm -> g_ha (pre-scaled)
    k_fgemm<false><<<T64_ALL, 256, FGEMM_SMEM>>>(g_hb, g_ha, W3, b2);
    // final aggregation + pooling + MLP
    k_agg    <<<AB, 256>>>(g_ha, b3);
    k_poolseg<<<PB, 128>>>(batch);
    k_mlp    <<<N_GRAPHS, 64>>>(Wm1, bm1, Wm2, bm2, out);
}

// round 14
// speedup vs baseline: 1.5906x; 1.5906x over previous
#include <cuda_runtime.h>
#include <cuda_bf16.h>
#include <cstdint>

#define N_NODES  50000
#define N_EDGES  800000
#define N_GRAPHS 64
#define IN_DIM   384
#define HID      128
#define SCB      196
#define T64_ALL  ((N_NODES + 63) / 64)       // 782

// ---- plain gemm smem (K-chunk staged A+B) ----
#define STG_A_LO 5120
#define STG_B_HI 10240
#define STG_B_LO 18944
#define STG_SZ   27648
#define GEMM_SMEM (2 * STG_SZ)

// ---- fused gemm smem: A fully staged (64x136 bf16 hi+lo), B double-buffered ----
#define FA_LO   17408
#define FB_BASE 34816
#define FB_STG  17408        // B_hi 8704 + B_lo 8704
#define FGEMM_SMEM (FB_BASE + 2 * FB_STG)   // 69632

// ================= streams/events =================
struct HxStreams {
    cudaStream_t s1;
    cudaEvent_t e_root, e_csr;
    HxStreams() {
        cudaStreamCreateWithFlags(&s1, cudaStreamNonBlocking);
        cudaEventCreateWithFlags(&e_root, cudaEventDisableTiming);
        cudaEventCreateWithFlags(&e_csr, cudaEventDisableTiming);
    }
};
static HxStreams g_hx;

// ================= scratch =================
__device__ float g_dis[N_NODES];
__device__ float g_ha[N_NODES * HID];
__device__ float g_hb[N_NODES * HID];
__device__ float g_act[N_NODES * HID];
__device__ float g_pool[N_GRAPHS * HID];
__device__ float g_cnt[N_GRAPHS];
__device__ int   g_cntarr[N_NODES];
__device__ int   g_scan[N_NODES];
__device__ int   g_bsum[256];
__device__ int   g_boff[256];
__device__ int   g_rowptr[N_NODES + 1];
__device__ int   g_cursor[N_NODES];
__device__ int   g_csrc[N_EDGES];

__device__ __forceinline__ uint32_t smem_u32(const void* p) {
    uint32_t a;
    asm("{ .reg .u64 t; cvta.to.shared.u64 t, %1; cvt.u32.u64 %0, t; }" : "=r"(a) : "l"(p));
    return a;
}
__device__ __forceinline__ void split2(float f0, float f1, uint32_t& h, uint32_t& l) {
    asm("cvt.rn.bf16x2.f32 %0, %1, %2;" : "=r"(h) : "f"(f1), "f"(f0));
    float h0 = __uint_as_float(h << 16);
    float h1 = __uint_as_float(h & 0xFFFF0000u);
    float l0 = f0 - h0, l1 = f1 - h1;
    asm("cvt.rn.bf16x2.f32 %0, %1, %2;" : "=r"(l) : "f"(l1), "f"(l0));
}

#define LDSM_X4(r, a)                                                          \
    asm volatile("ldmatrix.sync.aligned.m8n8.x4.shared.b16 {%0,%1,%2,%3}, [%4];" \
                 : "=r"((r)[0]), "=r"((r)[1]), "=r"((r)[2]), "=r"((r)[3]) : "r"(a))
#define LDSM_X4T(r, a)                                                         \
    asm volatile("ldmatrix.sync.aligned.m8n8.x4.trans.shared.b16 {%0,%1,%2,%3}, [%4];" \
                 : "=r"((r)[0]), "=r"((r)[1]), "=r"((r)[2]), "=r"((r)[3]) : "r"(a))
#define MMA_BF16(c, a, b0, b1)                                                 \
    asm volatile("mma.sync.aligned.m16n8k16.row.col.f32.bf16.bf16.f32 "        \
                 "{%0,%1,%2,%3}, {%4,%5,%6,%7}, {%8,%9}, {%0,%1,%2,%3};"       \
                 : "+f"((c)[0]), "+f"((c)[1]), "+f"((c)[2]), "+f"((c)[3])      \
                 : "r"((a)[0]), "r"((a)[1]), "r"((a)[2]), "r"((a)[3]),         \
                   "r"(b0), "r"(b1))

// ================= setup kernels =================
__global__ void k_zero() {
    int i = blockIdx.x * blockDim.x + threadIdx.x;
    if (i < N_NODES)        g_cntarr[i] = 0;
    if (i < N_GRAPHS * HID) g_pool[i] = 0.f;
    if (i < N_GRAPHS)       g_cnt[i] = 0.f;
}
__global__ void k_count_edges(const int* __restrict__ dst) {
    int e = blockIdx.x * blockDim.x + threadIdx.x;
    if (e < N_EDGES) atomicAdd(&g_cntarr[dst[e]], 1);
}
__global__ void k_scan1() {
    __shared__ int s[256];
    int tid = threadIdx.x;
    int i = blockIdx.x * 256 + tid;
    s[tid] = (i < N_NODES) ? g_cntarr[i] : 0;
    __syncthreads();
#pragma unroll
    for (int off = 1; off < 256; off <<= 1) {
        int t = (tid >= off) ? s[tid - off] : 0;
        __syncthreads();
        s[tid] += t;
        __syncthreads();
    }
    if (i < N_NODES) g_scan[i] = s[tid];
    if (tid == 255) g_bsum[blockIdx.x] = s[255];
}
__global__ void k_scan2() {
    __shared__ int s[256];
    int tid = threadIdx.x;
    int v = (tid < SCB) ? g_bsum[tid] : 0;
    s[tid] = v;
    __syncthreads();
#pragma unroll
    for (int off = 1; off < 256; off <<= 1) {
        int t = (tid >= off) ? s[tid - off] : 0;
        __syncthreads();
        s[tid] += t;
        __syncthreads();
    }
    g_boff[tid] = s[tid] - v;
}
__global__ void k_scan3() {
    int i = blockIdx.x * blockDim.x + threadIdx.x;
    if (i < N_NODES) {
        int cnt = g_cntarr[i];
        int S = g_scan[i] + g_boff[i >> 8];
        g_rowptr[i + 1] = S;
        g_cursor[i] = S - cnt;
        g_dis[i] = rsqrtf((float)cnt + 1.f);
        if (i == 0) g_rowptr[0] = 0;
    }
}
__global__ void k_fill(const int* __restrict__ src, const int* __restrict__ dst) {
    int e = blockIdx.x * blockDim.x + threadIdx.x;
    if (e < N_EDGES) {
        int d = dst[e];
        int pos = atomicAdd(&g_cursor[d], 1);
        g_csrc[pos] = src[e];
    }
}

// ================= plain split-bf16 GEMM (layer 1: x @ W1 -> g_ha raw) =================
template <int K>
__global__ void __launch_bounds__(256)
k_gemm(const float* __restrict__ A, const float* __restrict__ W, float* __restrict__ Hout) {
    extern __shared__ char smx[];
    const int tid = threadIdx.x;
    const int lane = tid & 31;
    const int wid = tid >> 5;
    const int wm = wid & 1;
    const int wn = wid >> 1;
    const int m0 = blockIdx.x * 64;

    const int ar = tid >> 2;
    const int ac = (tid & 3) * 8;
    const int br = tid >> 4;
    const int bc = (tid & 15) * 8;

    const uint32_t sbase = smem_u32(smx);
    float4 sa0, sa1, sb0, sb1, sb2, sb3;

    auto ldg_chunk = [&](int k0) {
        int row = m0 + ar;
        int rc = (row < N_NODES) ? row : (N_NODES - 1);
        const float* ap = A + (long)rc * K + k0 + ac;
        sa0 = *(const float4*)ap;
        sa1 = *(const float4*)(ap + 4);
        const float* bp = W + (long)(k0 + br) * 128 + bc;
        sb0 = *(const float4*)bp;
        sb1 = *(const float4*)(bp + 4);
        const float* bp2 = W + (long)(k0 + br + 16) * 128 + bc;
        sb2 = *(const float4*)bp2;
        sb3 = *(const float4*)(bp2 + 4);
    };
    auto sts_chunk = [&](int s) {
        char* base = smx + s * STG_SZ;
        uint32_t h0, h1, h2, h3, l0, l1, l2, l3;
        split2(sa0.x, sa0.y, h0, l0); split2(sa0.z, sa0.w, h1, l1);
        split2(sa1.x, sa1.y, h2, l2); split2(sa1.z, sa1.w, h3, l3);
        *(uint4*)(base + (ar * 40 + ac) * 2)            = make_uint4(h0, h1, h2, h3);
        *(uint4*)(base + STG_A_LO + (ar * 40 + ac) * 2) = make_uint4(l0, l1, l2, l3);
        split2(sb0.x, sb0.y, h0, l0); split2(sb0.z, sb0.w, h1, l1);
        split2(sb1.x, sb1.y, h2, l2); split2(sb1.z, sb1.w, h3, l3);
        *(uint4*)(base + STG_B_HI + (br * 136 + bc) * 2) = make_uint4(h0, h1, h2, h3);
        *(uint4*)(base + STG_B_LO + (br * 136 + bc) * 2) = make_uint4(l0, l1, l2, l3);
        split2(sb2.x, sb2.y, h0, l0); split2(sb2.z, sb2.w, h1, l1);
        split2(sb3.x, sb3.y, h2, l2); split2(sb3.z, sb3.w, h3, l3);
        *(uint4*)(base + STG_B_HI + ((br + 16) * 136 + bc) * 2) = make_uint4(h0, h1, h2, h3);
        *(uint4*)(base + STG_B_LO + ((br + 16) * 136 + bc) * 2) = make_uint4(l0, l1, l2, l3);
    };

    float c[2][4][4] = {};
    constexpr int NC = K / 32;
    ldg_chunk(0);
    sts_chunk(0);
    __syncthreads();
    if (NC > 1) ldg_chunk(32);

    for (int ch = 0; ch < NC; ch++) {
        if (ch + 1 < NC) sts_chunk((ch + 1) & 1);
        if (ch + 2 < NC) ldg_chunk((ch + 2) * 32);
        uint32_t st = sbase + (ch & 1) * STG_SZ;
#pragma unroll
        for (int ks = 0; ks < 2; ks++) {
            uint32_t Ah[2][4], Al[2][4], Bh[2][4], Bl[2][4];
#pragma unroll
            for (int mt = 0; mt < 2; mt++) {
                uint32_t row = wm * 32 + mt * 16 + (lane & 15);
                uint32_t col = ks * 16 + (lane >> 4) * 8;
                uint32_t ad = st + (row * 40 + col) * 2;
                LDSM_X4(Ah[mt], ad);
                LDSM_X4(Al[mt], ad + STG_A_LO);
            }
#pragma unroll
            for (int g2 = 0; g2 < 2; g2++) {
                uint32_t brow = ks * 16 + (lane & 15);
                uint32_t bcol = wn * 32 + g2 * 16 + (lane >> 4) * 8;
                uint32_t bd = st + STG_B_HI + (brow * 136 + bcol) * 2;
                LDSM_X4T(Bh[g2], bd);
                LDSM_X4T(Bl[g2], bd + (STG_B_LO - STG_B_HI));
            }
#pragma unroll
            for (int mt = 0; mt < 2; mt++)
#pragma unroll
                for (int nt = 0; nt < 4; nt++) {
                    uint32_t b0h = Bh[nt >> 1][(nt & 1) * 2], b1h = Bh[nt >> 1][(nt & 1) * 2 + 1];
                    uint32_t b0l = Bl[nt >> 1][(nt & 1) * 2], b1l = Bl[nt >> 1][(nt & 1) * 2 + 1];
                    MMA_BF16(c[mt][nt], Ah[mt], b0h, b1h);
                    MMA_BF16(c[mt][nt], Ah[mt], b0l, b1l);
                    MMA_BF16(c[mt][nt], Al[mt], b0h, b1h);
                }
        }
        __syncthreads();
    }

    const int g = lane >> 2, t = lane & 3;
#pragma unroll
    for (int mt = 0; mt < 2; mt++) {
        int r0 = m0 + wm * 32 + mt * 16 + g;
        int r1 = r0 + 8;
#pragma unroll
        for (int nt = 0; nt < 4; nt++) {
            int col = wn * 32 + nt * 8 + t * 2;
            if (r0 < N_NODES)
                *(float2*)&Hout[r0 * 128 + col] = make_float2(c[mt][nt][0], c[mt][nt][1]);
            if (r1 < N_NODES)
                *(float2*)&Hout[r1 * 128 + col] = make_float2(c[mt][nt][2], c[mt][nt][3]);
        }
    }
}

// ================= fused agg+GEMM (layers 2,3) =================
// Gather phase uses the k_agg access pattern: warp-per-node, lane owns 4 contiguous
// floats (coalesced 512B per neighbor row). Each warp processes 8 rows of the tile.
// A_eff[n] = relu( dn*( own + sum_neighbors ) + bias ) -> smem bf16 hi/lo.
// C = A_eff @ W; Hout = C * dis[row] (pre-scaled for the next layer).
template <bool WEIGHTED>
__global__ void __launch_bounds__(256)
k_fgemm(const float* __restrict__ Hin, float* __restrict__ Hout,
        const float* __restrict__ W, const float* __restrict__ bias) {
    extern __shared__ char smx[];
    const int tid = threadIdx.x;
    const int lane = tid & 31;
    const int wid = tid >> 5;
    const int wm = wid & 1;
    const int wn = wid >> 1;
    const int m0 = blockIdx.x * 64;

    const uint32_t sbase = smem_u32(smx);

    // ---- B staging ----
    const int br = tid >> 4;
    const int bc = (tid & 15) * 8;
    float4 sb0, sb1, sb2, sb3;
    auto ldgB = [&](int k0) {
        const float* bp = W + (long)(k0 + br) * 128 + bc;
        sb0 = *(const float4*)bp;
        sb1 = *(const float4*)(bp + 4);
        const float* bp2 = W + (long)(k0 + br + 16) * 128 + bc;
        sb2 = *(const float4*)bp2;
        sb3 = *(const float4*)(bp2 + 4);
    };
    auto stsB = [&](int s) {
        char* base = smx + FB_BASE + s * FB_STG;
        uint32_t h0, h1, h2, h3, l0, l1, l2, l3;
        split2(sb0.x, sb0.y, h0, l0); split2(sb0.z, sb0.w, h1, l1);
        split2(sb1.x, sb1.y, h2, l2); split2(sb1.z, sb1.w, h3, l3);
        *(uint4*)(base + (br * 136 + bc) * 2)        = make_uint4(h0, h1, h2, h3);
        *(uint4*)(base + 8704 + (br * 136 + bc) * 2) = make_uint4(l0, l1, l2, l3);
        split2(sb2.x, sb2.y, h0, l0); split2(sb2.z, sb2.w, h1, l1);
        split2(sb3.x, sb3.y, h2, l2); split2(sb3.z, sb3.w, h3, l3);
        *(uint4*)(base + ((br + 16) * 136 + bc) * 2)        = make_uint4(h0, h1, h2, h3);
        *(uint4*)(base + 8704 + ((br + 16) * 136 + bc) * 2) = make_uint4(l0, l1, l2, l3);
    };

    ldgB(0);   // chunk-0 B in flight during the gather

    // ---- gather + activation: warp-per-node, 8 nodes per warp ----
    {
        const int l4 = lane * 4;
        const float4 b = *(const float4*)&bias[l4];
        for (int r = 0; r < 8; r++) {
            int row = wid * 8 + r;
            int n = m0 + row;
            int nc_ = (n < N_NODES) ? n : (N_NODES - 1);
            int rp0 = g_rowptr[nc_], rp1 = g_rowptr[nc_ + 1];
            float dn = g_dis[nc_];

            float4 acc = *(const float4*)&Hin[(long)nc_ * 128 + l4];
            if (WEIGHTED) { acc.x *= dn; acc.y *= dn; acc.z *= dn; acc.w *= dn; }

            int i = rp0;
            if (WEIGHTED) {
                for (; i + 1 < rp1; i += 2) {
                    int s0 = g_csrc[i], s1 = g_csrc[i + 1];
                    float w0 = g_dis[s0], w1 = g_dis[s1];
                    float4 v0 = *(const float4*)&Hin[(long)s0 * 128 + l4];
                    float4 v1 = *(const float4*)&Hin[(long)s1 * 128 + l4];
                    acc.x += v0.x * w0 + v1.x * w1;
                    acc.y += v0.y * w0 + v1.y * w1;
                    acc.z += v0.z * w0 + v1.z * w1;
                    acc.w += v0.w * w0 + v1.w * w1;
                }
                if (i < rp1) {
                    int s0 = g_csrc[i];
                    float w0 = g_dis[s0];
                    float4 v0 = *(const float4*)&Hin[(long)s0 * 128 + l4];
                    acc.x += v0.x * w0; acc.y += v0.y * w0;
                    acc.z += v0.z * w0; acc.w += v0.w * w0;
                }
            } else {
                for (; i + 3 < rp1; i += 4) {
                    int s0 = g_csrc[i], s1 = g_csrc[i + 1], s2 = g_csrc[i + 2], s3 = g_csrc[i + 3];
                    float4 v0 = *(const float4*)&Hin[(long)s0 * 128 + l4];
                    float4 v1 = *(const float4*)&Hin[(long)s1 * 128 + l4];
                    float4 v2 = *(const float4*)&Hin[(long)s2 * 128 + l4];
                    float4 v3 = *(const float4*)&Hin[(long)s3 * 128 + l4];
                    acc.x += (v0.x + v1.x) + (v2.x + v3.x);
                    acc.y += (v0.y + v1.y) + (v2.y + v3.y);
                    acc.z += (v0.z + v1.z) + (v2.z + v3.z);
                    acc.w += (v0.w + v1.w) + (v2.w + v3.w);
                }
                for (; i < rp1; i++) {
                    int s0 = g_csrc[i];
                    float4 v0 = *(const float4*)&Hin[(long)s0 * 128 + l4];
                    acc.x += v0.x; acc.y += v0.y; acc.z += v0.z; acc.w += v0.w;
                }
            }

            float a0 = fmaxf(fmaf(acc.x, dn, b.x), 0.f);
            float a1 = fmaxf(fmaf(acc.y, dn, b.y), 0.f);
            float a2 = fmaxf(fmaf(acc.z, dn, b.z), 0.f);
            float a3 = fmaxf(fmaf(acc.w, dn, b.w), 0.f);
            uint32_t h0, h1, l0, l1;
            split2(a0, a1, h0, l0);
            split2(a2, a3, h1, l1);
            int off = (row * 136 + l4) * 2;
            *(uint2*)(smx + off)         = make_uint2(h0, h1);
            *(uint2*)(smx + FA_LO + off) = make_uint2(l0, l1);
        }
    }

    stsB(0);
    __syncthreads();
    ldgB(32);

    float c[2][4][4] = {};
    for (int ch = 0; ch < 4; ch++) {
        if (ch + 1 < 4) stsB((ch + 1) & 1);
        if (ch + 2 < 4) ldgB((ch + 2) * 32);
        uint32_t st = sbase + FB_BASE + (ch & 1) * FB_STG;
#pragma unroll
        for (int ks = 0; ks < 2; ks++) {
            uint32_t Ah[2][4], Al[2][4], Bh[2][4], Bl[2][4];
#pragma unroll
            for (int mt = 0; mt < 2; mt++) {
                uint32_t row = wm * 32 + mt * 16 + (lane & 15);
                uint32_t col = ch * 32 + ks * 16 + (lane >> 4) * 8;
                uint32_t ad = sbase + (row * 136 + col) * 2;
                LDSM_X4(Ah[mt], ad);
                LDSM_X4(Al[mt], ad + FA_LO);
            }
#pragma unroll
            for (int g2 = 0; g2 < 2; g2++) {
                uint32_t brow = ks * 16 + (lane & 15);
                uint32_t bcol = wn * 32 + g2 * 16 + (lane >> 4) * 8;
                uint32_t bd = st + (brow * 136 + bcol) * 2;
                LDSM_X4T(Bh[g2], bd);
                LDSM_X4T(Bl[g2], bd + 8704);
            }
#pragma unroll
            for (int mt = 0; mt < 2; mt++)
#pragma unroll
                for (int nt = 0; nt < 4; nt++) {
                    uint32_t b0h = Bh[nt >> 1][(nt & 1) * 2], b1h = Bh[nt >> 1][(nt & 1) * 2 + 1];
                    uint32_t b0l = Bl[nt >> 1][(nt & 1) * 2], b1l = Bl[nt >> 1][(nt & 1) * 2 + 1];
                    MMA_BF16(c[mt][nt], Ah[mt], b0h, b1h);
                    MMA_BF16(c[mt][nt], Ah[mt], b0l, b1l);
                    MMA_BF16(c[mt][nt], Al[mt], b0h, b1h);
                }
        }
        __syncthreads();
    }

    const int g = lane >> 2, t = lane & 3;
#pragma unroll
    for (int mt = 0; mt < 2; mt++) {
        int r0 = m0 + wm * 32 + mt * 16 + g;
        int r1 = r0 + 8;
        float s0 = (r0 < N_NODES) ? g_dis[r0] : 0.f;
        float s1 = (r1 < N_NODES) ? g_dis[r1] : 0.f;
#pragma unroll
        for (int nt = 0; nt < 4; nt++) {
            int col = wn * 32 + nt * 8 + t * 2;
            if (r0 < N_NODES)
                *(float2*)&Hout[r0 * 128 + col] = make_float2(c[mt][nt][0] * s0, c[mt][nt][1] * s0);
            if (r1 < N_NODES)
                *(float2*)&Hout[r1 * 128 + col] = make_float2(c[mt][nt][2] * s1, c[mt][nt][3] * s1);
        }
    }
}

// ================= final aggregation (layer 3, h pre-scaled) =================
__global__ void __launch_bounds__(256)
k_agg(const float* __restrict__ Hin, const float* __restrict__ bias) {
    int wid = threadIdx.x >> 5;
    int lane = threadIdx.x & 31;
    int node = blockIdx.x * 8 + wid;
    if (node >= N_NODES) return;

    int rp0 = g_rowptr[node];
    int rp1 = g_rowptr[node + 1];
    float dn = g_dis[node];
    int l4 = lane * 4;

    float4 acc = *(const float4*)&Hin[node * 128 + l4];
    int i = rp0;
    for (; i + 3 < rp1; i += 4) {
        int s0 = g_csrc[i], s1 = g_csrc[i + 1], s2 = g_csrc[i + 2], s3 = g_csrc[i + 3];
        float4 v0 = *(const float4*)&Hin[s0 * 128 + l4];
        float4 v1 = *(const float4*)&Hin[s1 * 128 + l4];
        float4 v2 = *(const float4*)&Hin[s2 * 128 + l4];
        float4 v3 = *(const float4*)&Hin[s3 * 128 + l4];
        acc.x += (v0.x + v1.x) + (v2.x + v3.x);
        acc.y += (v0.y + v1.y) + (v2.y + v3.y);
        acc.z += (v0.z + v1.z) + (v2.z + v3.z);
        acc.w += (v0.w + v1.w) + (v2.w + v3.w);
    }
    for (; i < rp1; i++) {
        int s0 = g_csrc[i];
        float4 v0 = *(const float4*)&Hin[s0 * 128 + l4];
        acc.x += v0.x; acc.y += v0.y; acc.z += v0.z; acc.w += v0.w;
    }

    float4 b = *(const float4*)&bias[l4];
    acc.x = fmaxf(fmaf(acc.x, dn, b.x), 0.f);
    acc.y = fmaxf(fmaf(acc.y, dn, b.y), 0.f);
    acc.z = fmaxf(fmaf(acc.z, dn, b.z), 0.f);
    acc.w = fmaxf(fmaf(acc.w, dn, b.w), 0.f);
    *(float4*)&g_act[node * 128 + l4] = acc;
}

// ================= pooling + MLP =================
__global__ void __launch_bounds__(128)
k_poolseg(const int* __restrict__ batch) {
    __shared__ int sb[128];
    int t = threadIdx.x;
    int n0 = blockIdx.x * 128;
    int cnt = min(128, N_NODES - n0);
    if (t < cnt) sb[t] = batch[n0 + t];
    __syncthreads();

    float acc = 0.f;
    int cur = sb[0];
    int segstart = 0;
    for (int i = 0; i < cnt; i++) {
        int g = sb[i];
        if (g != cur) {
            atomicAdd(&g_pool[cur * 128 + t], acc);
            if (t == 0) atomicAdd(&g_cnt[cur], (float)(i - segstart));
            acc = 0.f;
            cur = g;
            segstart = i;
        }
        acc += g_act[(n0 + i) * 128 + t];
    }
    atomicAdd(&g_pool[cur * 128 + t], acc);
    if (t == 0) atomicAdd(&g_cnt[cur], (float)(cnt - segstart));
}

__global__ void k_mlp(const float* __restrict__ Wm1, const float* __restrict__ bm1,
                      const float* __restrict__ Wm2, const float* __restrict__ bm2,
                      float* __restrict__ out) {
    int g = blockIdx.x;
    int j = threadIdx.x;
    __shared__ float p[128];
    __shared__ float red[64];
    float cnt = fmaxf(g_cnt[g], 1.f);
    p[j] = g_pool[g * 128 + j] / cnt;
    p[j + 64] = g_pool[g * 128 + 64 + j] / cnt;
    __syncthreads();
    float z = bm1[j];
#pragma unroll 8
    for (int k = 0; k < 128; k++) z = fmaf(p[k], Wm1[k * 64 + j], z);
    z = fmaxf(z, 0.f);
    z *= Wm2[j];
    red[j] = z;
    __syncthreads();
#pragma unroll
    for (int s = 32; s > 0; s >>= 1) {
        if (j < s) red[j] += red[j + s];
        __syncthreads();
    }
    if (j == 0) out[g] = red[0] + bm2[0];
}

// ================= launch =================
extern "C" void kernel_launch(void* const* d_in, const int* in_sizes, int n_in,
                              void* d_out, int out_size) {
    const float* x    = (const float*)d_in[0];
    const int*   ei   = (const int*)  d_in[1];
    const int*   batch= (const int*)  d_in[2];
    const float* W1   = (const float*)d_in[3];
    const float* b1   = (const float*)d_in[4];
    const float* W2   = (const float*)d_in[5];
    const float* b2   = (const float*)d_in[6];
    const float* W3   = (const float*)d_in[7];
    const float* b3   = (const float*)d_in[8];
    const float* Wm1  = (const float*)d_in[9];
    const float* bm1  = (const float*)d_in[10];
    const float* Wm2  = (const float*)d_in[11];
    const float* bm2  = (const float*)d_in[12];
    const int* src = ei;
    const int* dst = ei + N_EDGES;
    float* out = (float*)d_out;
    cudaStream_t s1 = g_hx.s1;

    cudaFuncSetAttribute(k_gemm<IN_DIM>,  cudaFuncAttributeMaxDynamicSharedMemorySize, GEMM_SMEM);
    cudaFuncSetAttribute(k_fgemm<true>,   cudaFuncAttributeMaxDynamicSharedMemorySize, FGEMM_SMEM);
    cudaFuncSetAttribute(k_fgemm<false>,  cudaFuncAttributeMaxDynamicSharedMemorySize, FGEMM_SMEM);

    const int EB = (N_EDGES + 255) / 256;
    const int AB = (N_NODES + 7) / 8;
    const int PB = (N_NODES + 127) / 128;

    // fork: CSR build on s1 || layer-1 GEMM on s0
    cudaEventRecord(g_hx.e_root, 0);
    cudaStreamWaitEvent(s1, g_hx.e_root, 0);

    k_zero       <<<SCB, 256, 0, s1>>>();
    k_count_edges<<<EB, 256, 0, s1>>>(dst);
    k_scan1      <<<SCB, 256, 0, s1>>>();
    k_scan2      <<<1, 256, 0, s1>>>();
    k_scan3      <<<SCB, 256, 0, s1>>>();
    k_fill       <<<EB, 256, 0, s1>>>(src, dst);
    cudaEventRecord(g_hx.e_csr, s1);

    k_gemm<IN_DIM><<<T64_ALL, 256, GEMM_SMEM>>>(x, W1, g_ha);

    cudaStreamWaitEvent(0, g_hx.e_csr, 0);

    // layer 2: fused agg(h_a raw, weighted) + gemm -> g_hb (pre-scaled)
    k_fgemm<true><<<T64_ALL, 256, FGEMM_SMEM>>>(g_ha, g_hb, W2, b1);
    // layer 3: fused agg(h_b pre-scaled) + gemm -> g_ha (pre-scaled)
    k_fgemm<false><<<T64_ALL, 256, FGEMM_SMEM>>>(g_hb, g_ha, W3, b2);
    // final aggregation + pooling + MLP
    k_agg    <<<AB, 256>>>(g_ha, b3);
    k_poolseg<<<PB, 128>>>(batch);
    k_mlp    <<<N_GRAPHS, 64>>>(Wm1, bm1, Wm2, bm2, out);
}

// round 15
// speedup vs baseline: 39.3465x; 24.7368x over previous
#include <cuda_runtime.h>
#include <cuda_bf16.h>
#include <cstdint>

#define N_NODES  50000
#define N_EDGES  800000
#define N_GRAPHS 64
#define IN_DIM   384
#define HID      128
#define SCB      196
#define T64_ALL  ((N_NODES + 63) / 64)       // 782

// ---- plain gemm smem (K-chunk staged A+B) ----
#define STG_A_LO 5120
#define STG_B_HI 10240
#define STG_B_LO 18944
#define STG_SZ   27648
#define GEMM_SMEM (2 * STG_SZ)

// ---- fused gemm smem: A fully staged (64x136 bf16 hi+lo), B double-buffered ----
#define FA_LO   17408
#define FB_BASE 34816
#define FB_STG  17408        // B_hi 8704 + B_lo 8704
#define FGEMM_SMEM (FB_BASE + 2 * FB_STG)   // 69632

// ================= streams/events =================
struct HxStreams {
    cudaStream_t s1;
    cudaEvent_t e_root, e_csr;
    HxStreams() {
        cudaStreamCreateWithFlags(&s1, cudaStreamNonBlocking);
        cudaEventCreateWithFlags(&e_root, cudaEventDisableTiming);
        cudaEventCreateWithFlags(&e_csr, cudaEventDisableTiming);
    }
};
static HxStreams g_hx;

// ================= scratch (device-side only; NEVER passed from host) =================
__device__ float g_dis[N_NODES];
__device__ float g_ha[N_NODES * HID];
__device__ float g_hb[N_NODES * HID];
__device__ float g_act[N_NODES * HID];
__device__ float g_pool[N_GRAPHS * HID];
__device__ float g_cnt[N_GRAPHS];
__device__ int   g_cntarr[N_NODES];
__device__ int   g_scan[N_NODES];
__device__ int   g_bsum[256];
__device__ int   g_boff[256];
__device__ int   g_rowptr[N_NODES + 1];
__device__ int   g_cursor[N_NODES];
__device__ int   g_csrc[N_EDGES];

__device__ __forceinline__ uint32_t smem_u32(const void* p) {
    uint32_t a;
    asm("{ .reg .u64 t; cvta.to.shared.u64 t, %1; cvt.u32.u64 %0, t; }" : "=r"(a) : "l"(p));
    return a;
}
__device__ __forceinline__ void split2(float f0, float f1, uint32_t& h, uint32_t& l) {
    asm("cvt.rn.bf16x2.f32 %0, %1, %2;" : "=r"(h) : "f"(f1), "f"(f0));
    float h0 = __uint_as_float(h << 16);
    float h1 = __uint_as_float(h & 0xFFFF0000u);
    float l0 = f0 - h0, l1 = f1 - h1;
    asm("cvt.rn.bf16x2.f32 %0, %1, %2;" : "=r"(l) : "f"(l1), "f"(l0));
}

#define LDSM_X4(r, a)                                                          \
    asm volatile("ldmatrix.sync.aligned.m8n8.x4.shared.b16 {%0,%1,%2,%3}, [%4];" \
                 : "=r"((r)[0]), "=r"((r)[1]), "=r"((r)[2]), "=r"((r)[3]) : "r"(a))
#define LDSM_X4T(r, a)                                                         \
    asm volatile("ldmatrix.sync.aligned.m8n8.x4.trans.shared.b16 {%0,%1,%2,%3}, [%4];" \
                 : "=r"((r)[0]), "=r"((r)[1]), "=r"((r)[2]), "=r"((r)[3]) : "r"(a))
#define MMA_BF16(c, a, b0, b1)                                                 \
    asm volatile("mma.sync.aligned.m16n8k16.row.col.f32.bf16.bf16.f32 "        \
                 "{%0,%1,%2,%3}, {%4,%5,%6,%7}, {%8,%9}, {%0,%1,%2,%3};"       \
                 : "+f"((c)[0]), "+f"((c)[1]), "+f"((c)[2]), "+f"((c)[3])      \
                 : "r"((a)[0]), "r"((a)[1]), "r"((a)[2]), "r"((a)[3]),         \
                   "r"(b0), "r"(b1))

// ================= setup kernels =================
__global__ void k_zero() {
    int i = blockIdx.x * blockDim.x + threadIdx.x;
    if (i < N_NODES)        g_cntarr[i] = 0;
    if (i < N_GRAPHS * HID) g_pool[i] = 0.f;
    if (i < N_GRAPHS)       g_cnt[i] = 0.f;
}
__global__ void k_count_edges(const int* __restrict__ dst) {
    int e = blockIdx.x * blockDim.x + threadIdx.x;
    if (e < N_EDGES) atomicAdd(&g_cntarr[dst[e]], 1);
}
__global__ void k_scan1() {
    __shared__ int s[256];
    int tid = threadIdx.x;
    int i = blockIdx.x * 256 + tid;
    s[tid] = (i < N_NODES) ? g_cntarr[i] : 0;
    __syncthreads();
#pragma unroll
    for (int off = 1; off < 256; off <<= 1) {
        int t = (tid >= off) ? s[tid - off] : 0;
        __syncthreads();
        s[tid] += t;
        __syncthreads();
    }
    if (i < N_NODES) g_scan[i] = s[tid];
    if (tid == 255) g_bsum[blockIdx.x] = s[255];
}
__global__ void k_scan2() {
    __shared__ int s[256];
    int tid = threadIdx.x;
    int v = (tid < SCB) ? g_bsum[tid] : 0;
    s[tid] = v;
    __syncthreads();
#pragma unroll
    for (int off = 1; off < 256; off <<= 1) {
        int t = (tid >= off) ? s[tid - off] : 0;
        __syncthreads();
        s[tid] += t;
        __syncthreads();
    }
    g_boff[tid] = s[tid] - v;
}
__global__ void k_scan3() {
    int i = blockIdx.x * blockDim.x + threadIdx.x;
    if (i < N_NODES) {
        int cnt = g_cntarr[i];
        int S = g_scan[i] + g_boff[i >> 8];
        g_rowptr[i + 1] = S;
        g_cursor[i] = S - cnt;
        g_dis[i] = rsqrtf((float)cnt + 1.f);
        if (i == 0) g_rowptr[0] = 0;
    }
}
__global__ void k_fill(const int* __restrict__ src, const int* __restrict__ dst) {
    int e = blockIdx.x * blockDim.x + threadIdx.x;
    if (e < N_EDGES) {
        int d = dst[e];
        int pos = atomicAdd(&g_cursor[d], 1);
        g_csrc[pos] = src[e];
    }
}

// ================= plain split-bf16 GEMM (layer 1: x @ W1 -> g_ha raw) =================
template <int K>
__global__ void __launch_bounds__(256)
k_gemm(const float* __restrict__ A, const float* __restrict__ W) {
    extern __shared__ char smx[];
    float* Hout = g_ha;
    const int tid = threadIdx.x;
    const int lane = tid & 31;
    const int wid = tid >> 5;
    const int wm = wid & 1;
    const int wn = wid >> 1;
    const int m0 = blockIdx.x * 64;

    const int ar = tid >> 2;
    const int ac = (tid & 3) * 8;
    const int br = tid >> 4;
    const int bc = (tid & 15) * 8;

    const uint32_t sbase = smem_u32(smx);
    float4 sa0, sa1, sb0, sb1, sb2, sb3;

    auto ldg_chunk = [&](int k0) {
        int row = m0 + ar;
        int rc = (row < N_NODES) ? row : (N_NODES - 1);
        const float* ap = A + (long)rc * K + k0 + ac;
        sa0 = *(const float4*)ap;
        sa1 = *(const float4*)(ap + 4);
        const float* bp = W + (long)(k0 + br) * 128 + bc;
        sb0 = *(const float4*)bp;
        sb1 = *(const float4*)(bp + 4);
        const float* bp2 = W + (long)(k0 + br + 16) * 128 + bc;
        sb2 = *(const float4*)bp2;
        sb3 = *(const float4*)(bp2 + 4);
    };
    auto sts_chunk = [&](int s) {
        char* base = smx + s * STG_SZ;
        uint32_t h0, h1, h2, h3, l0, l1, l2, l3;
        split2(sa0.x, sa0.y, h0, l0); split2(sa0.z, sa0.w, h1, l1);
        split2(sa1.x, sa1.y, h2, l2); split2(sa1.z, sa1.w, h3, l3);
        *(uint4*)(base + (ar * 40 + ac) * 2)            = make_uint4(h0, h1, h2, h3);
        *(uint4*)(base + STG_A_LO + (ar * 40 + ac) * 2) = make_uint4(l0, l1, l2, l3);
        split2(sb0.x, sb0.y, h0, l0); split2(sb0.z, sb0.w, h1, l1);
        split2(sb1.x, sb1.y, h2, l2); split2(sb1.z, sb1.w, h3, l3);
        *(uint4*)(base + STG_B_HI + (br * 136 + bc) * 2) = make_uint4(h0, h1, h2, h3);
        *(uint4*)(base + STG_B_LO + (br * 136 + bc) * 2) = make_uint4(l0, l1, l2, l3);
        split2(sb2.x, sb2.y, h0, l0); split2(sb2.z, sb2.w, h1, l1);
        split2(sb3.x, sb3.y, h2, l2); split2(sb3.z, sb3.w, h3, l3);
        *(uint4*)(base + STG_B_HI + ((br + 16) * 136 + bc) * 2) = make_uint4(h0, h1, h2, h3);
        *(uint4*)(base + STG_B_LO + ((br + 16) * 136 + bc) * 2) = make_uint4(l0, l1, l2, l3);
    };

    float c[2][4][4] = {};
    constexpr int NC = K / 32;
    ldg_chunk(0);
    sts_chunk(0);
    __syncthreads();
    if (NC > 1) ldg_chunk(32);

    for (int ch = 0; ch < NC; ch++) {
        if (ch + 1 < NC) sts_chunk((ch + 1) & 1);
        if (ch + 2 < NC) ldg_chunk((ch + 2) * 32);
        uint32_t st = sbase + (ch & 1) * STG_SZ;
#pragma unroll
        for (int ks = 0; ks < 2; ks++) {
            uint32_t Ah[2][4], Al[2][4], Bh[2][4], Bl[2][4];
#pragma unroll
            for (int mt = 0; mt < 2; mt++) {
                uint32_t row = wm * 32 + mt * 16 + (lane & 15);
                uint32_t col = ks * 16 + (lane >> 4) * 8;
                uint32_t ad = st + (row * 40 + col) * 2;
                LDSM_X4(Ah[mt], ad);
                LDSM_X4(Al[mt], ad + STG_A_LO);
            }
#pragma unroll
            for (int g2 = 0; g2 < 2; g2++) {
                uint32_t brow = ks * 16 + (lane & 15);
                uint32_t bcol = wn * 32 + g2 * 16 + (lane >> 4) * 8;
                uint32_t bd = st + STG_B_HI + (brow * 136 + bcol) * 2;
                LDSM_X4T(Bh[g2], bd);
                LDSM_X4T(Bl[g2], bd + (STG_B_LO - STG_B_HI));
            }
#pragma unroll
            for (int mt = 0; mt < 2; mt++)
#pragma unroll
                for (int nt = 0; nt < 4; nt++) {
                    uint32_t b0h = Bh[nt >> 1][(nt & 1) * 2], b1h = Bh[nt >> 1][(nt & 1) * 2 + 1];
                    uint32_t b0l = Bl[nt >> 1][(nt & 1) * 2], b1l = Bl[nt >> 1][(nt & 1) * 2 + 1];
                    MMA_BF16(c[mt][nt], Ah[mt], b0h, b1h);
                    MMA_BF16(c[mt][nt], Ah[mt], b0l, b1l);
                    MMA_BF16(c[mt][nt], Al[mt], b0h, b1h);
                }
        }
        __syncthreads();
    }

    const int g = lane >> 2, t = lane & 3;
#pragma unroll
    for (int mt = 0; mt < 2; mt++) {
        int r0 = m0 + wm * 32 + mt * 16 + g;
        int r1 = r0 + 8;
#pragma unroll
        for (int nt = 0; nt < 4; nt++) {
            int col = wn * 32 + nt * 8 + t * 2;
            if (r0 < N_NODES)
                *(float2*)&Hout[r0 * 128 + col] = make_float2(c[mt][nt][0], c[mt][nt][1]);
            if (r1 < N_NODES)
                *(float2*)&Hout[r1 * 128 + col] = make_float2(c[mt][nt][2], c[mt][nt][3]);
        }
    }
}

// ================= fused agg+GEMM (layers 2,3) =================
// DIR=0: Hin=g_ha, Hout=g_hb; DIR=1: Hin=g_hb, Hout=g_ha. Resolved in-kernel.
// Gather: warp-per-node, lane owns 4 contiguous floats; 8 nodes per warp.
// A_eff[n] = relu( dn*( own + sum_neighbors ) + bias ) -> smem bf16 hi/lo.
// C = A_eff @ W; Hout = C * dis[row] (pre-scaled for the next layer).
template <bool WEIGHTED, int DIR>
__global__ void __launch_bounds__(256)
k_fgemm(const float* __restrict__ W, const float* __restrict__ bias) {
    extern __shared__ char smx[];
    const float* Hin = DIR ? g_hb : g_ha;
    float* Hout      = DIR ? g_ha : g_hb;

    const int tid = threadIdx.x;
    const int lane = tid & 31;
    const int wid = tid >> 5;
    const int wm = wid & 1;
    const int wn = wid >> 1;
    const int m0 = blockIdx.x * 64;

    const uint32_t sbase = smem_u32(smx);

    // ---- B staging ----
    const int br = tid >> 4;
    const int bc = (tid & 15) * 8;
    float4 sb0, sb1, sb2, sb3;
    auto ldgB = [&](int k0) {
        const float* bp = W + (long)(k0 + br) * 128 + bc;
        sb0 = *(const float4*)bp;
        sb1 = *(const float4*)(bp + 4);
        const float* bp2 = W + (long)(k0 + br + 16) * 128 + bc;
        sb2 = *(const float4*)bp2;
        sb3 = *(const float4*)(bp2 + 4);
    };
    auto stsB = [&](int s) {
        char* base = smx + FB_BASE + s * FB_STG;
        uint32_t h0, h1, h2, h3, l0, l1, l2, l3;
        split2(sb0.x, sb0.y, h0, l0); split2(sb0.z, sb0.w, h1, l1);
        split2(sb1.x, sb1.y, h2, l2); split2(sb1.z, sb1.w, h3, l3);
        *(uint4*)(base + (br * 136 + bc) * 2)        = make_uint4(h0, h1, h2, h3);
        *(uint4*)(base + 8704 + (br * 136 + bc) * 2) = make_uint4(l0, l1, l2, l3);
        split2(sb2.x, sb2.y, h0, l0); split2(sb2.z, sb2.w, h1, l1);
        split2(sb3.x, sb3.y, h2, l2); split2(sb3.z, sb3.w, h3, l3);
        *(uint4*)(base + ((br + 16) * 136 + bc) * 2)        = make_uint4(h0, h1, h2, h3);
        *(uint4*)(base + 8704 + ((br + 16) * 136 + bc) * 2) = make_uint4(l0, l1, l2, l3);
    };

    ldgB(0);   // chunk-0 B in flight during the gather

    // ---- gather + activation: warp-per-node, 8 nodes per warp ----
    {
        const int l4 = lane * 4;
        const float4 b = *(const float4*)&bias[l4];
        for (int r = 0; r < 8; r++) {
            int row = wid * 8 + r;
            int n = m0 + row;
            int nc_ = (n < N_NODES) ? n : (N_NODES - 1);
            int rp0 = g_rowptr[nc_], rp1 = g_rowptr[nc_ + 1];
            float dn = g_dis[nc_];

            float4 acc = *(const float4*)&Hin[(long)nc_ * 128 + l4];
            if (WEIGHTED) { acc.x *= dn; acc.y *= dn; acc.z *= dn; acc.w *= dn; }

            int i = rp0;
            if (WEIGHTED) {
                for (; i + 1 < rp1; i += 2) {
                    int s0 = g_csrc[i], s1 = g_csrc[i + 1];
                    float w0 = g_dis[s0], w1 = g_dis[s1];
                    float4 v0 = *(const float4*)&Hin[(long)s0 * 128 + l4];
                    float4 v1 = *(const float4*)&Hin[(long)s1 * 128 + l4];
                    acc.x += v0.x * w0 + v1.x * w1;
                    acc.y += v0.y * w0 + v1.y * w1;
                    acc.z += v0.z * w0 + v1.z * w1;
                    acc.w += v0.w * w0 + v1.w * w1;
                }
                if (i < rp1) {
                    int s0 = g_csrc[i];
                    float w0 = g_dis[s0];
                    float4 v0 = *(const float4*)&Hin[(long)s0 * 128 + l4];
                    acc.x += v0.x * w0; acc.y += v0.y * w0;
                    acc.z += v0.z * w0; acc.w += v0.w * w0;
                }
            } else {
                for (; i + 3 < rp1; i += 4) {
                    int s0 = g_csrc[i], s1 = g_csrc[i + 1], s2 = g_csrc[i + 2], s3 = g_csrc[i + 3];
                    float4 v0 = *(const float4*)&Hin[(long)s0 * 128 + l4];
                    float4 v1 = *(const float4*)&Hin[(long)s1 * 128 + l4];
                    float4 v2 = *(const float4*)&Hin[(long)s2 * 128 + l4];
                    float4 v3 = *(const float4*)&Hin[(long)s3 * 128 + l4];
                    acc.x += (v0.x + v1.x) + (v2.x + v3.x);
                    acc.y += (v0.y + v1.y) + (v2.y + v3.y);
                    acc.z += (v0.z + v1.z) + (v2.z + v3.z);
                    acc.w += (v0.w + v1.w) + (v2.w + v3.w);
                }
                for (; i < rp1; i++) {
                    int s0 = g_csrc[i];
                    float4 v0 = *(const float4*)&Hin[(long)s0 * 128 + l4];
                    acc.x += v0.x; acc.y += v0.y; acc.z += v0.z; acc.w += v0.w;
                }
            }

            float a0 = fmaxf(fmaf(acc.x, dn, b.x), 0.f);
            float a1 = fmaxf(fmaf(acc.y, dn, b.y), 0.f);
            float a2 = fmaxf(fmaf(acc.z, dn, b.z), 0.f);
            float a3 = fmaxf(fmaf(acc.w, dn, b.w), 0.f);
            uint32_t h0, h1, l0, l1;
            split2(a0, a1, h0, l0);
            split2(a2, a3, h1, l1);
            int off = (row * 136 + l4) * 2;
            *(uint2*)(smx + off)         = make_uint2(h0, h1);
            *(uint2*)(smx + FA_LO + off) = make_uint2(l0, l1);
        }
    }

    stsB(0);
    __syncthreads();
    ldgB(32);

    float c[2][4][4] = {};
    for (int ch = 0; ch < 4; ch++) {
        if (ch + 1 < 4) stsB((ch + 1) & 1);
        if (ch + 2 < 4) ldgB((ch + 2) * 32);
        uint32_t st = sbase + FB_BASE + (ch & 1) * FB_STG;
#pragma unroll
        for (int ks = 0; ks < 2; ks++) {
            uint32_t Ah[2][4], Al[2][4], Bh[2][4], Bl[2][4];
#pragma unroll
            for (int mt = 0; mt < 2; mt++) {
                uint32_t row = wm * 32 + mt * 16 + (lane & 15);
                uint32_t col = ch * 32 + ks * 16 + (lane >> 4) * 8;
                uint32_t ad = sbase + (row * 136 + col) * 2;
                LDSM_X4(Ah[mt], ad);
                LDSM_X4(Al[mt], ad + FA_LO);
            }
#pragma unroll
            for (int g2 = 0; g2 < 2; g2++) {
                uint32_t brow = ks * 16 + (lane & 15);
                uint32_t bcol = wn * 32 + g2 * 16 + (lane >> 4) * 8;
                uint32_t bd = st + (brow * 136 + bcol) * 2;
                LDSM_X4T(Bh[g2], bd);
                LDSM_X4T(Bl[g2], bd + 8704);
            }
#pragma unroll
            for (int mt = 0; mt < 2; mt++)
#pragma unroll
                for (int nt = 0; nt < 4; nt++) {
                    uint32_t b0h = Bh[nt >> 1][(nt & 1) * 2], b1h = Bh[nt >> 1][(nt & 1) * 2 + 1];
                    uint32_t b0l = Bl[nt >> 1][(nt & 1) * 2], b1l = Bl[nt >> 1][(nt & 1) * 2 + 1];
                    MMA_BF16(c[mt][nt], Ah[mt], b0h, b1h);
                    MMA_BF16(c[mt][nt], Ah[mt], b0l, b1l);
                    MMA_BF16(c[mt][nt], Al[mt], b0h, b1h);
                }
        }
        __syncthreads();
    }

    const int g = lane >> 2, t = lane & 3;
#pragma unroll
    for (int mt = 0; mt < 2; mt++) {
        int r0 = m0 + wm * 32 + mt * 16 + g;
        int r1 = r0 + 8;
        float s0 = (r0 < N_NODES) ? g_dis[r0] : 0.f;
        float s1 = (r1 < N_NODES) ? g_dis[r1] : 0.f;
#pragma unroll
        for (int nt = 0; nt < 4; nt++) {
            int col = wn * 32 + nt * 8 + t * 2;
            if (r0 < N_NODES)
                *(float2*)&Hout[r0 * 128 + col] = make_float2(c[mt][nt][0] * s0, c[mt][nt][1] * s0);
            if (r1 < N_NODES)
                *(float2*)&Hout[r1 * 128 + col] = make_float2(c[mt][nt][2] * s1, c[mt][nt][3] * s1);
        }
    }
}

// ================= final aggregation (layer 3 output in g_ha, pre-scaled) =================
__global__ void __launch_bounds__(256)
k_agg(const float* __restrict__ bias) {
    const float* Hin = g_ha;
    int wid = threadIdx.x >> 5;
    int lane = threadIdx.x & 31;
    int node = blockIdx.x * 8 + wid;
    if (node >= N_NODES) return;

    int rp0 = g_rowptr[node];
    int rp1 = g_rowptr[node + 1];
    float dn = g_dis[node];
    int l4 = lane * 4;

    float4 acc = *(const float4*)&Hin[node * 128 + l4];
    int i = rp0;
    for (; i + 3 < rp1; i += 4) {
        int s0 = g_csrc[i], s1 = g_csrc[i + 1], s2 = g_csrc[i + 2], s3 = g_csrc[i + 3];
        float4 v0 = *(const float4*)&Hin[s0 * 128 + l4];
        float4 v1 = *(const float4*)&Hin[s1 * 128 + l4];
        float4 v2 = *(const float4*)&Hin[s2 * 128 + l4];
        float4 v3 = *(const float4*)&Hin[s3 * 128 + l4];
        acc.x += (v0.x + v1.x) + (v2.x + v3.x);
        acc.y += (v0.y + v1.y) + (v2.y + v3.y);
        acc.z += (v0.z + v1.z) + (v2.z + v3.z);
        acc.w += (v0.w + v1.w) + (v2.w + v3.w);
    }
    for (; i < rp1; i++) {
        int s0 = g_csrc[i];
        float4 v0 = *(const float4*)&Hin[s0 * 128 + l4];
        acc.x += v0.x; acc.y += v0.y; acc.z += v0.z; acc.w += v0.w;
    }

    float4 b = *(const float4*)&bias[l4];
    acc.x = fmaxf(fmaf(acc.x, dn, b.x), 0.f);
    acc.y = fmaxf(fmaf(acc.y, dn, b.y), 0.f);
    acc.z = fmaxf(fmaf(acc.z, dn, b.z), 0.f);
    acc.w = fmaxf(fmaf(acc.w, dn, b.w), 0.f);
    *(float4*)&g_act[node * 128 + l4] = acc;
}

// ================= pooling + MLP =================
__global__ void __launch_bounds__(128)
k_poolseg(const int* __restrict__ batch) {
    __shared__ int sb[128];
    int t = threadIdx.x;
    int n0 = blockIdx.x * 128;
    int cnt = min(128, N_NODES - n0);
    if (t < cnt) sb[t] = batch[n0 + t];
    __syncthreads();

    float acc = 0.f;
    int cur = sb[0];
    int segstart = 0;
    for (int i = 0; i < cnt; i++) {
        int g = sb[i];
        if (g != cur) {
            atomicAdd(&g_pool[cur * 128 + t], acc);
            if (t == 0) atomicAdd(&g_cnt[cur], (float)(i - segstart));
            acc = 0.f;
            cur = g;
            segstart = i;
        }
        acc += g_act[(n0 + i) * 128 + t];
    }
    atomicAdd(&g_pool[cur * 128 + t], acc);
    if (t == 0) atomicAdd(&g_cnt[cur], (float)(cnt - segstart));
}

__global__ void k_mlp(const float* __restrict__ Wm1, const float* __restrict__ bm1,
                      const float* __restrict__ Wm2, const float* __restrict__ bm2,
                      float* __restrict__ out) {
    int g = blockIdx.x;
    int j = threadIdx.x;
    __shared__ float p[128];
    __shared__ float red[64];
    float cnt = fmaxf(g_cnt[g], 1.f);
    p[j] = g_pool[g * 128 + j] / cnt;
    p[j + 64] = g_pool[g * 128 + 64 + j] / cnt;
    __syncthreads();
    float z = bm1[j];
#pragma unroll 8
    for (int k = 0; k < 128; k++) z = fmaf(p[k], Wm1[k * 64 + j], z);
    z = fmaxf(z, 0.f);
    z *= Wm2[j];
    red[j] = z;
    __syncthreads();
#pragma unroll
    for (int s = 32; s > 0; s >>= 1) {
        if (j < s) red[j] += red[j + s];
        __syncthreads();
    }
    if (j == 0) out[g] = red[0] + bm2[0];
}

// ================= launch =================
extern "C" void kernel_launch(void* const* d_in, const int* in_sizes, int n_in,
                              void* d_out, int out_size) {
    const float* x    = (const float*)d_in[0];
    const int*   ei   = (const int*)  d_in[1];
    const int*   batch= (const int*)  d_in[2];
    const float* W1   = (const float*)d_in[3];
    const float* b1   = (const float*)d_in[4];
    const float* W2   = (const float*)d_in[5];
    const float* b2   = (const float*)d_in[6];
    const float* W3   = (const float*)d_in[7];
    const float* b3   = (const float*)d_in[8];
    const float* Wm1  = (const float*)d_in[9];
    const float* bm1  = (const float*)d_in[10];
    const float* Wm2  = (const float*)d_in[11];
    const float* bm2  = (const float*)d_in[12];
    const int* src = ei;
    const int* dst = ei + N_EDGES;
    float* out = (float*)d_out;
    cudaStream_t s1 = g_hx.s1;

    cudaFuncSetAttribute(k_gemm<IN_DIM>,     cudaFuncAttributeMaxDynamicSharedMemorySize, GEMM_SMEM);
    cudaFuncSetAttribute(k_fgemm<true, 0>,   cudaFuncAttributeMaxDynamicSharedMemorySize, FGEMM_SMEM);
    cudaFuncSetAttribute(k_fgemm<false, 1>,  cudaFuncAttributeMaxDynamicSharedMemorySize, FGEMM_SMEM);

    const int EB = (N_EDGES + 255) / 256;
    const int AB = (N_NODES + 7) / 8;
    const int PB = (N_NODES + 127) / 128;

    // fork: CSR build on s1 || layer-1 GEMM on s0
    cudaEventRecord(g_hx.e_root, 0);
    cudaStreamWaitEvent(s1, g_hx.e_root, 0);

    k_zero       <<<SCB, 256, 0, s1>>>();
    k_count_edges<<<EB, 256, 0, s1>>>(dst);
    k_scan1      <<<SCB, 256, 0, s1>>>();
    k_scan2      <<<1, 256, 0, s1>>>();
    k_scan3      <<<SCB, 256, 0, s1>>>();
    k_fill       <<<EB, 256, 0, s1>>>(src, dst);
    cudaEventRecord(g_hx.e_csr, s1);

    k_gemm<IN_DIM><<<T64_ALL, 256, GEMM_SMEM>>>(x, W1);   // -> g_ha (raw)

    cudaStreamWaitEvent(0, g_hx.e_csr, 0);

    // layer 2: fused agg(g_ha raw, weighted) + gemm -> g_hb (pre-scaled)
    k_fgemm<true, 0><<<T64_ALL, 256, FGEMM_SMEM>>>(W2, b1);
    // layer 3: fused agg(g_hb pre-scaled) + gemm -> g_ha (pre-scaled)
    k_fgemm<false, 1><<<T64_ALL, 256, FGEMM_SMEM>>>(W3, b2);
    // final aggregation + pooling + MLP
    k_agg    <<<AB, 256>>>(b3);
    k_poolseg<<<PB, 128>>>(batch);
    k_mlp    <<<N_GRAPHS, 64>>>(Wm1, bm1, Wm2, bm2, out);
}

// round 17
// speedup vs baseline: 49.6098x; 1.2608x over previous
#include <cuda_runtime.h>
#include <cuda_bf16.h>
#include <cstdint>

#define N_NODES  50000
#define N_EDGES  800000
#define N_GRAPHS 64
#define IN_DIM   384
#define HID      128
#define SCB      196

#define H0_TILES 196
#define H0_NODES (H0_TILES * 128)            // 25088
#define H1_NODES (N_NODES - H0_NODES)        // 24912
#define H1_TILES ((H1_NODES + 127) / 128)    // 195

// smem layout (bytes, per stage): A_hi[128][40]bf16=10240, A_lo=10240, B_hi[32][136]bf16=8704, B_lo=8704
#define STG_A_LO 10240
#define STG_B_HI 20480
#define STG_B_LO 29184
#define STG_SZ   37888
#define GEMM_SMEM (2 * STG_SZ)

// ================= streams/events =================
struct HxStreams {
    cudaStream_t s1;
    cudaEvent_t e_root, e_csr, e_g1, eA, eB, eC, eD, eF;
    HxStreams() {
        cudaStreamCreateWithFlags(&s1, cudaStreamNonBlocking);
        cudaEvent_t* evs[8] = {&e_root, &e_csr, &e_g1, &eA, &eB, &eC, &eD, &eF};
        for (int i = 0; i < 8; i++) cudaEventCreateWithFlags(evs[i], cudaEventDisableTiming);
    }
};
static HxStreams g_hx;

// ================= scratch (device-side only; NEVER passed from host) =================
__device__ float g_dis[N_NODES];
__device__ float g_h[N_NODES * HID];
__device__ float g_act[N_NODES * HID];
__device__ float g_pool[N_GRAPHS * HID];
__device__ float g_cnt[N_GRAPHS];
__device__ int   g_cntarr[N_NODES];
__device__ int   g_scan[N_NODES];
__device__ int   g_bsum[256];
__device__ int   g_boff[256];
__device__ int   g_rowptr[N_NODES + 1];
__device__ int   g_cursor[N_NODES];
__device__ int   g_csrc[N_EDGES];

__device__ __forceinline__ uint32_t smem_u32(const void* p) {
    uint32_t a;
    asm("{ .reg .u64 t; cvta.to.shared.u64 t, %1; cvt.u32.u64 %0, t; }" : "=r"(a) : "l"(p));
    return a;
}

// pack (f0,f1) -> bf16x2 hi + residual lo
__device__ __forceinline__ void split2(float f0, float f1, uint32_t& h, uint32_t& l) {
    asm("cvt.rn.bf16x2.f32 %0, %1, %2;" : "=r"(h) : "f"(f1), "f"(f0));
    float h0 = __uint_as_float(h << 16);
    float h1 = __uint_as_float(h & 0xFFFF0000u);
    float l0 = f0 - h0, l1 = f1 - h1;
    asm("cvt.rn.bf16x2.f32 %0, %1, %2;" : "=r"(l) : "f"(l1), "f"(l0));
}

#define LDSM_X4(r, a)                                                          \
    asm volatile("ldmatrix.sync.aligned.m8n8.x4.shared.b16 {%0,%1,%2,%3}, [%4];" \
                 : "=r"((r)[0]), "=r"((r)[1]), "=r"((r)[2]), "=r"((r)[3]) : "r"(a))
#define LDSM_X4T(r, a)                                                         \
    asm volatile("ldmatrix.sync.aligned.m8n8.x4.trans.shared.b16 {%0,%1,%2,%3}, [%4];" \
                 : "=r"((r)[0]), "=r"((r)[1]), "=r"((r)[2]), "=r"((r)[3]) : "r"(a))
#define MMA_BF16(c, a, b0, b1)                                                 \
    asm volatile("mma.sync.aligned.m16n8k16.row.col.f32.bf16.bf16.f32 "        \
                 "{%0,%1,%2,%3}, {%4,%5,%6,%7}, {%8,%9}, {%0,%1,%2,%3};"       \
                 : "+f"((c)[0]), "+f"((c)[1]), "+f"((c)[2]), "+f"((c)[3])      \
                 : "r"((a)[0]), "r"((a)[1]), "r"((a)[2]), "r"((a)[3]),         \
                   "r"(b0), "r"(b1))

// ================= setup kernels =================
__global__ void k_zero() {
    int i = blockIdx.x * blockDim.x + threadIdx.x;
    if (i < N_NODES)        g_cntarr[i] = 0;
    if (i < N_GRAPHS * HID) g_pool[i] = 0.f;
    if (i < N_GRAPHS)       g_cnt[i] = 0.f;
}
__global__ void k_count_edges(const int* __restrict__ dst) {
    int e = blockIdx.x * blockDim.x + threadIdx.x;
    if (e < N_EDGES) atomicAdd(&g_cntarr[dst[e]], 1);
}
__global__ void k_scan1() {
    __shared__ int s[256];
    int tid = threadIdx.x;
    int i = blockIdx.x * 256 + tid;
    s[tid] = (i < N_NODES) ? g_cntarr[i] : 0;
    __syncthreads();
#pragma unroll
    for (int off = 1; off < 256; off <<= 1) {
        int t = (tid >= off) ? s[tid - off] : 0;
        __syncthreads();
        s[tid] += t;
        __syncthreads();
    }
    if (i < N_NODES) g_scan[i] = s[tid];
    if (tid == 255) g_bsum[blockIdx.x] = s[255];
}
__global__ void k_scan2() {
    __shared__ int s[256];
    int tid = threadIdx.x;
    int v = (tid < SCB) ? g_bsum[tid] : 0;
    s[tid] = v;
    __syncthreads();
#pragma unroll
    for (int off = 1; off < 256; off <<= 1) {
        int t = (tid >= off) ? s[tid - off] : 0;
        __syncthreads();
        s[tid] += t;
        __syncthreads();
    }
    g_boff[tid] = s[tid] - v;
}
__global__ void k_scan3() {
    int i = blockIdx.x * blockDim.x + threadIdx.x;
    if (i < N_NODES) {
        int cnt = g_cntarr[i];
        int S = g_scan[i] + g_boff[i >> 8];
        g_rowptr[i + 1] = S;
        g_cursor[i] = S - cnt;
        g_dis[i] = rsqrtf((float)cnt + 1.f);
        if (i == 0) g_rowptr[0] = 0;
    }
}
__global__ void k_fill(const int* __restrict__ src, const int* __restrict__ dst) {
    int e = blockIdx.x * blockDim.x + threadIdx.x;
    if (e < N_EDGES) {
        int d = dst[e];
        int pos = atomicAdd(&g_cursor[d], 1);
        g_csrc[pos] = src[e];
    }
}

// ================= split-bf16 mma.sync GEMM (R10: 128-row CTA tile, 512 threads) ========
// g_h[tile rows, 128] = A @ W ; optional row-scale by g_dis.
// warp grid 4m x 4n, warp tile 32x32 (m16n8k16).
template <int K, bool FOLD_DIS>
__global__ void __launch_bounds__(512, 1)
k_gemm(const float* __restrict__ Aext, const float* __restrict__ W, int m0base) {
    extern __shared__ char smx[];
    const float* A = Aext ? Aext : g_act;

    const int tid = threadIdx.x;
    const int lane = tid & 31;
    const int wid = tid >> 5;           // 0..15
    const int wm = wid & 3;             // 4 m-warps * 32 rows
    const int wn = wid >> 2;            // 4 n-warps * 32 cols
    const int m0 = m0base + blockIdx.x * 128;

    const int ar = tid >> 2;            // A row 0..127
    const int ac = (tid & 3) * 8;       // A col (within 32-chunk)
    const int br = tid >> 4;            // B row 0..31
    const int bc = (tid & 15) * 8;      // B col 0..120

    const uint32_t sbase = smem_u32(smx);

    float4 sa0, sa1, sb0, sb1;

    auto ldg_chunk = [&](int k0) {
        int row = m0 + ar;
        int rc = (row < N_NODES) ? row : (N_NODES - 1);
        const float* ap = A + (long)rc * K + k0 + ac;
        sa0 = *(const float4*)ap;
        sa1 = *(const float4*)(ap + 4);
        const float* bp = W + (long)(k0 + br) * 128 + bc;
        sb0 = *(const float4*)bp;
        sb1 = *(const float4*)(bp + 4);
    };
    auto sts_chunk = [&](int s) {
        char* base = smx + s * STG_SZ;
        uint32_t h0, h1, h2, h3, l0, l1, l2, l3;
        split2(sa0.x, sa0.y, h0, l0); split2(sa0.z, sa0.w, h1, l1);
        split2(sa1.x, sa1.y, h2, l2); split2(sa1.z, sa1.w, h3, l3);
        *(uint4*)(base + (ar * 40 + ac) * 2)            = make_uint4(h0, h1, h2, h3);
        *(uint4*)(base + STG_A_LO + (ar * 40 + ac) * 2) = make_uint4(l0, l1, l2, l3);
        split2(sb0.x, sb0.y, h0, l0); split2(sb0.z, sb0.w, h1, l1);
        split2(sb1.x, sb1.y, h2, l2); split2(sb1.z, sb1.w, h3, l3);
        *(uint4*)(base + STG_B_HI + (br * 136 + bc) * 2) = make_uint4(h0, h1, h2, h3);
        *(uint4*)(base + STG_B_LO + (br * 136 + bc) * 2) = make_uint4(l0, l1, l2, l3);
    };

    float c[2][4][4] = {};

    constexpr int NC = K / 32;
    ldg_chunk(0);
    sts_chunk(0);
    __syncthreads();
    if (NC > 1) ldg_chunk(32);

    for (int ch = 0; ch < NC; ch++) {
        if (ch + 1 < NC) sts_chunk((ch + 1) & 1);
        if (ch + 2 < NC) ldg_chunk((ch + 2) * 32);

        uint32_t st = sbase + (ch & 1) * STG_SZ;
#pragma unroll
        for (int ks = 0; ks < 2; ks++) {
            uint32_t Ah[2][4], Al[2][4], Bh[2][4], Bl[2][4];
#pragma unroll
            for (int mt = 0; mt < 2; mt++) {
                uint32_t row = wm * 32 + mt * 16 + (lane & 15);
                uint32_t col = ks * 16 + (lane >> 4) * 8;
                uint32_t ad = st + (row * 40 + col) * 2;
                LDSM_X4(Ah[mt], ad);
                LDSM_X4(Al[mt], ad + STG_A_LO);
            }
#pragma unroll
            for (int g2 = 0; g2 < 2; g2++) {
                uint32_t brow = ks * 16 + (lane & 15);
                uint32_t bcol = wn * 32 + g2 * 16 + (lane >> 4) * 8;
                uint32_t bd = st + STG_B_HI + (brow * 136 + bcol) * 2;
                LDSM_X4T(Bh[g2], bd);
                LDSM_X4T(Bl[g2], bd + (STG_B_LO - STG_B_HI));
            }
#pragma unroll
            for (int mt = 0; mt < 2; mt++)
#pragma unroll
                for (int nt = 0; nt < 4; nt++) {
                    uint32_t b0h = Bh[nt >> 1][(nt & 1) * 2], b1h = Bh[nt >> 1][(nt & 1) * 2 + 1];
                    uint32_t b0l = Bl[nt >> 1][(nt & 1) * 2], b1l = Bl[nt >> 1][(nt & 1) * 2 + 1];
                    MMA_BF16(c[mt][nt], Ah[mt], b0h, b1h);
                    MMA_BF16(c[mt][nt], Ah[mt], b0l, b1l);
                    MMA_BF16(c[mt][nt], Al[mt], b0h, b1h);
                }
        }
        __syncthreads();
    }

    // epilogue
    const int g = lane >> 2, t = lane & 3;
#pragma unroll
    for (int mt = 0; mt < 2; mt++) {
        int r0 = m0 + wm * 32 + mt * 16 + g;
        int r1 = r0 + 8;
        float s0 = 1.f, s1 = 1.f;
        if (FOLD_DIS) {
            if (r0 < N_NODES) s0 = g_dis[r0];
            if (r1 < N_NODES) s1 = g_dis[r1];
        }
#pragma unroll
        for (int nt = 0; nt < 4; nt++) {
            int col = wn * 32 + nt * 8 + t * 2;
            if (r0 < N_NODES)
                *(float2*)&g_h[r0 * 128 + col] = make_float2(c[mt][nt][0] * s0, c[mt][nt][1] * s0);
            if (r1 < N_NODES)
                *(float2*)&g_h[r1 * 128 + col] = make_float2(c[mt][nt][2] * s1, c[mt][nt][3] * s1);
        }
    }
}

// ================= CSR aggregation: warp per node (layers 1,2) =================
template <bool WEIGHTED>
__global__ void __launch_bounds__(256)
k_agg(const float* __restrict__ bias, int base, int ncount) {
    int wid = threadIdx.x >> 5;
    int lane = threadIdx.x & 31;
    int node = base + blockIdx.x * 8 + wid;
    if (node >= base + ncount) return;

    int rp0 = g_rowptr[node];
    int rp1 = g_rowptr[node + 1];
    float dn = g_dis[node];
    int l4 = lane * 4;

    float4 acc = *(const float4*)&g_h[node * 128 + l4];
    if (WEIGHTED) { acc.x *= dn; acc.y *= dn; acc.z *= dn; acc.w *= dn; }

    int i = rp0;
    if (WEIGHTED) {
        for (; i + 1 < rp1; i += 2) {
            int s0 = g_csrc[i], s1 = g_csrc[i + 1];
            float w0 = g_dis[s0], w1 = g_dis[s1];
            float4 v0 = *(const float4*)&g_h[s0 * 128 + l4];
            float4 v1 = *(const float4*)&g_h[s1 * 128 + l4];
            acc.x += v0.x * w0 + v1.x * w1;
            acc.y += v0.y * w0 + v1.y * w1;
            acc.z += v0.z * w0 + v1.z * w1;
            acc.w += v0.w * w0 + v1.w * w1;
        }
        if (i < rp1) {
            int s0 = g_csrc[i];
            float w0 = g_dis[s0];
            float4 v0 = *(const float4*)&g_h[s0 * 128 + l4];
            acc.x += v0.x * w0; acc.y += v0.y * w0;
            acc.z += v0.z * w0; acc.w += v0.w * w0;
        }
    } else {
        for (; i + 3 < rp1; i += 4) {
            int s0 = g_csrc[i], s1 = g_csrc[i + 1], s2 = g_csrc[i + 2], s3 = g_csrc[i + 3];
            float4 v0 = *(const float4*)&g_h[s0 * 128 + l4];
            float4 v1 = *(const float4*)&g_h[s1 * 128 + l4];
            float4 v2 = *(const float4*)&g_h[s2 * 128 + l4];
            float4 v3 = *(const float4*)&g_h[s3 * 128 + l4];
            acc.x += (v0.x + v1.x) + (v2.x + v3.x);
            acc.y += (v0.y + v1.y) + (v2.y + v3.y);
            acc.z += (v0.z + v1.z) + (v2.z + v3.z);
            acc.w += (v0.w + v1.w) + (v2.w + v3.w);
        }
        for (; i < rp1; i++) {
            int s0 = g_csrc[i];
            float4 v0 = *(const float4*)&g_h[s0 * 128 + l4];
            acc.x += v0.x; acc.y += v0.y; acc.z += v0.z; acc.w += v0.w;
        }
    }

    float4 b = *(const float4*)&bias[l4];
    acc.x = fmaxf(fmaf(acc.x, dn, b.x), 0.f);
    acc.y = fmaxf(fmaf(acc.y, dn, b.y), 0.f);
    acc.z = fmaxf(fmaf(acc.z, dn, b.z), 0.f);
    acc.w = fmaxf(fmaf(acc.w, dn, b.w), 0.f);
    *(float4*)&g_act[node * 128 + l4] = acc;
}

// ================= fused layer-3 aggregation + pooling =================
// warp-per-node (h pre-scaled): act = relu(dn*(h[n] + sum_s h[s]) + b3),
// accumulated in per-block smem pool buffer (8 sorted nodes -> g-gmin in [0,7],
// rare out-of-range falls back to direct global RED), then one flush per graph-row.
__global__ void __launch_bounds__(256)
k_aggpool(const float* __restrict__ bias, int base, int ncount,
          const int* __restrict__ batch) {
    __shared__ float sbuf[8][128];
    __shared__ float scnt[8];
    int tid = threadIdx.x, wid = tid >> 5, lane = tid & 31;
    int node = base + blockIdx.x * 8 + wid;

    for (int i = tid; i < 8 * 128; i += 256) ((float*)sbuf)[i] = 0.f;
    if (tid < 8) scnt[tid] = 0.f;
    __syncthreads();

    int gmin = batch[base + blockIdx.x * 8];
    int l4 = lane * 4;

    if (node < base + ncount) {
        int rp0 = g_rowptr[node];
        int rp1 = g_rowptr[node + 1];
        float dn = g_dis[node];

        float4 acc = *(const float4*)&g_h[node * 128 + l4];
        int i = rp0;
        for (; i + 3 < rp1; i += 4) {
            int s0 = g_csrc[i], s1 = g_csrc[i + 1], s2 = g_csrc[i + 2], s3 = g_csrc[i + 3];
            float4 v0 = *(const float4*)&g_h[s0 * 128 + l4];
            float4 v1 = *(const float4*)&g_h[s1 * 128 + l4];
            float4 v2 = *(const float4*)&g_h[s2 * 128 + l4];
            float4 v3 = *(const float4*)&g_h[s3 * 128 + l4];
            acc.x += (v0.x + v1.x) + (v2.x + v3.x);
            acc.y += (v0.y + v1.y) + (v2.y + v3.y);
            acc.z += (v0.z + v1.z) + (v2.z + v3.z);
            acc.w += (v0.w + v1.w) + (v2.w + v3.w);
        }
        for (; i < rp1; i++) {
            int s0 = g_csrc[i];
            float4 v0 = *(const float4*)&g_h[s0 * 128 + l4];
            acc.x += v0.x; acc.y += v0.y; acc.z += v0.z; acc.w += v0.w;
        }

        float4 b = *(const float4*)&bias[l4];
        acc.x = fmaxf(fmaf(acc.x, dn, b.x), 0.f);
        acc.y = fmaxf(fmaf(acc.y, dn, b.y), 0.f);
        acc.z = fmaxf(fmaf(acc.z, dn, b.z), 0.f);
        acc.w = fmaxf(fmaf(acc.w, dn, b.w), 0.f);

        int g = batch[node];
        int gl = g - gmin;
        if (gl < 8) {
            atomicAdd(&sbuf[gl][l4 + 0], acc.x);
            atomicAdd(&sbuf[gl][l4 + 1], acc.y);
            atomicAdd(&sbuf[gl][l4 + 2], acc.z);
            atomicAdd(&sbuf[gl][l4 + 3], acc.w);
            if (lane == 0) atomicAdd(&scnt[gl], 1.f);
        } else {
            // impossible in practice (would need 7+ empty graphs); safe fallback
            float* p = &g_pool[g * 128 + l4];
            asm volatile("red.global.add.v4.f32 [%0], {%1,%2,%3,%4};"
                         :: "l"(p), "f"(acc.x), "f"(acc.y), "f"(acc.z), "f"(acc.w) : "memory");
            if (lane == 0) atomicAdd(&g_cnt[g], 1.f);
        }
    }
    __syncthreads();

    float cnt = scnt[wid];
    if (cnt > 0.f) {
        float4 v = *(const float4*)&sbuf[wid][l4];
        float* p = &g_pool[(gmin + wid) * 128 + l4];
        asm volatile("red.global.add.v4.f32 [%0], {%1,%2,%3,%4};"
                     :: "l"(p), "f"(v.x), "f"(v.y), "f"(v.z), "f"(v.w) : "memory");
        if (lane == 0) atomicAdd(&g_cnt[gmin + wid], cnt);
    }
}

__global__ void k_mlp(const float* __restrict__ Wm1, const float* __restrict__ bm1,
                      const float* __restrict__ Wm2, const float* __restrict__ bm2,
                      float* __restrict__ out) {
    int g = blockIdx.x;
    int j = threadIdx.x;
    __shared__ float p[128];
    __shared__ float red[64];
    float cnt = fmaxf(g_cnt[g], 1.f);
    p[j] = g_pool[g * 128 + j] / cnt;
    p[j + 64] = g_pool[g * 128 + 64 + j] / cnt;
    __syncthreads();
    float z = bm1[j];
#pragma unroll 8
    for (int k = 0; k < 128; k++) z = fmaf(p[k], Wm1[k * 64 + j], z);
    z = fmaxf(z, 0.f);
    z *= Wm2[j];
    red[j] = z;
    __syncthreads();
#pragma unroll
    for (int s = 32; s > 0; s >>= 1) {
        if (j < s) red[j] += red[j + s];
        __syncthreads();
    }
    if (j == 0) out[g] = red[0] + bm2[0];
}

// ================= launch =================
extern "C" void kernel_launch(void* const* d_in, const int* in_sizes, int n_in,
                              void* d_out, int out_size) {
    const float* x    = (const float*)d_in[0];
    const int*   ei   = (const int*)  d_in[1];
    const int*   batch= (const int*)  d_in[2];
    const float* W1   = (const float*)d_in[3];
    const float* b1   = (const float*)d_in[4];
    const float* W2   = (const float*)d_in[5];
    const float* b2   = (const float*)d_in[6];
    const float* W3   = (const float*)d_in[7];
    const float* b3   = (const float*)d_in[8];
    const float* Wm1  = (const float*)d_in[9];
    const float* bm1  = (const float*)d_in[10];
    const float* Wm2  = (const float*)d_in[11];
    const float* bm2  = (const float*)d_in[12];
    const int* src = ei;
    const int* dst = ei + N_EDGES;
    float* out = (float*)d_out;
    cudaStream_t s1 = g_hx.s1;

    cudaFuncSetAttribute(k_gemm<IN_DIM, false>, cudaFuncAttributeMaxDynamicSharedMemorySize, GEMM_SMEM);
    cudaFuncSetAttribute(k_gemm<HID, true>,     cudaFuncAttributeMaxDynamicSharedMemorySize, GEMM_SMEM);

    const int EB  = (N_EDGES + 255) / 256;
    const int TB  = (N_NODES + 127) / 128;     // 391
    const int AB0 = (H0_NODES + 7) / 8;        // 3136
    const int AB1 = (H1_NODES + 7) / 8;        // 3114

    // ---- fork: CSR build on s1 || layer-1 GEMM on stream 0 ----
    cudaEventRecord(g_hx.e_root, 0);
    cudaStreamWaitEvent(s1, g_hx.e_root, 0);

    k_zero       <<<SCB, 256, 0, s1>>>();
    k_count_edges<<<EB, 256, 0, s1>>>(dst);
    k_scan1      <<<SCB, 256, 0, s1>>>();
    k_scan2      <<<1, 256, 0, s1>>>();
    k_scan3      <<<SCB, 256, 0, s1>>>();
    k_fill       <<<EB, 256, 0, s1>>>(src, dst);
    cudaEventRecord(g_hx.e_csr, s1);

    k_gemm<IN_DIM, false><<<TB, 512, GEMM_SMEM>>>(x, W1, 0);
    cudaEventRecord(g_hx.e_g1, 0);

    cudaStreamWaitEvent(0, g_hx.e_csr, 0);
    cudaStreamWaitEvent(s1, g_hx.e_g1, 0);

    // ---- layer 1 agg + layer 2 gemm, half-pipelined ----
    k_agg<true><<<AB0, 256>>>(b1, 0, H0_NODES);
    k_gemm<HID, true><<<H0_TILES, 512, GEMM_SMEM>>>(nullptr, W2, 0);
    cudaEventRecord(g_hx.eA, 0);
    k_agg<true><<<AB1, 256, 0, s1>>>(b1, H0_NODES, H1_NODES);
    k_gemm<HID, true><<<H1_TILES, 512, GEMM_SMEM, s1>>>(nullptr, W2, H0_NODES);
    cudaEventRecord(g_hx.eB, s1);
    cudaStreamWaitEvent(0, g_hx.eB, 0);
    cudaStreamWaitEvent(s1, g_hx.eA, 0);

    // ---- layer 2 agg + layer 3 gemm ----
    k_agg<false><<<AB0, 256>>>(b2, 0, H0_NODES);
    k_gemm<HID, true><<<H0_TILES, 512, GEMM_SMEM>>>(nullptr, W3, 0);
    cudaEventRecord(g_hx.eC, 0);
    k_agg<false><<<AB1, 256, 0, s1>>>(b2, H0_NODES, H1_NODES);
    k_gemm<HID, true><<<H1_TILES, 512, GEMM_SMEM, s1>>>(nullptr, W3, H0_NODES);
    cudaEventRecord(g_hx.eD, s1);
    cudaStreamWaitEvent(0, g_hx.eD, 0);
    cudaStreamWaitEvent(s1, g_hx.eC, 0);

    // ---- layer 3: fused agg + pool, per half ----
    k_aggpool<<<AB0, 256>>>(b3, 0, H0_NODES, batch);
    k_aggpool<<<AB1, 256, 0, s1>>>(b3, H0_NODES, H1_NODES, batch);
    cudaEventRecord(g_hx.eF, s1);
    cudaStreamWaitEvent(0, g_hx.eF, 0);

    // ---- MLP ----
    k_mlp<<<N_GRAPHS, 64>>>(Wm1, bm1, Wm2, bm2, out);
}